// round 2
// baseline (speedup 1.0000x reference)
#include <cuda_runtime.h>
#include <cstdint>
#include <math.h>

#define DEVFN static __device__ __forceinline__

// ---------------- problem constants ----------------
constexpr int NN = 12000;
constexpr int FF = 256;

// ---------------- GEMM tiling ----------------------
constexpr int BM = 64;
constexpr int BN = 256;          // full output width: A read exactly once
constexpr int BK = 16;
constexpr int STAGES = 3;
constexpr int PAD = 20;          // floats per smem row (16 data + 4 pad) -> conflict-free frags
constexpr int A_WORDS = BM * PAD;              // 1280
constexpr int B_WORDS = BN * PAD;              // 5120
constexpr int STAGE_WORDS = A_WORDS + B_WORDS; // 6400 (25600 B)
constexpr int DYN_SMEM = STAGES * STAGE_WORDS * 4;  // 76800 B

// ---------------- device scratch -------------------
__device__ float g_scores[NN];
__device__ float g_p[NN];
__device__ float g_scaledT[(size_t)FF * NN];   // [256, 12000] B for GEMM1 (tf32-rounded)
__device__ float g_support4[(size_t)NN * FF];  // [12000, 256] A for GEMM2 (tf32-rounded)
__device__ float g_supportT[(size_t)FF * NN];  // [256, 12000] B for GEMM3 (tf32-rounded)
__device__ float g_weightT[FF * FF];           // [256, 256]   B for GEMM2 (tf32-rounded)

// ---------------- PTX helpers ----------------------
DEVFN uint32_t smem_u32(const void* p) {
    uint32_t a;
    asm("{ .reg .u64 t; cvta.to.shared.u64 t, %1; cvt.u32.u64 %0, t; }" : "=r"(a) : "l"(p));
    return a;
}
DEVFN void cp_async16(uint32_t saddr, const void* gaddr, int srcsize) {
    asm volatile("cp.async.cg.shared.global [%0], [%1], 16, %2;"
                 :: "r"(saddr), "l"(gaddr), "r"(srcsize) : "memory");
}
DEVFN void cp_commit() { asm volatile("cp.async.commit_group;" ::: "memory"); }
template <int N> DEVFN void cp_wait() { asm volatile("cp.async.wait_group %0;" :: "n"(N) : "memory"); }

// round fp32 -> tf32 (round-to-nearest-even on the 10-bit mantissa), bits in u32
DEVFN uint32_t f2tf32(float x) {
    uint32_t r; asm("cvt.rna.tf32.f32 %0, %1;" : "=r"(r) : "f"(x)); return r;
}
DEVFN float rnd_tf32(float x) { return __uint_as_float(f2tf32(x)); }

DEVFN void mma_tf32(float* c, const uint32_t* a, const uint32_t* b) {
    asm volatile(
        "mma.sync.aligned.m16n8k8.row.col.f32.tf32.tf32.f32 "
        "{%0,%1,%2,%3}, {%4,%5,%6,%7}, {%8,%9}, {%0,%1,%2,%3};"
        : "+f"(c[0]), "+f"(c[1]), "+f"(c[2]), "+f"(c[3])
        : "r"(a[0]), "r"(a[1]), "r"(a[2]), "r"(a[3]), "r"(b[0]), "r"(b[1]));
}

// ========================================================================
// GEMM: D[M, 256] = A[M, K] @ B[256, K]^T  (tf32 mma.sync, fp32 accum)
//   mode 0: C[r, c]      = tf32( D + alpha * inp[r, c] )   -> support4
//   mode 1: C[c*NN + r]  = tf32( D )                       -> supportT
//   mode 2: C[r, c]      = D                               -> final output
// ========================================================================
__global__ void __launch_bounds__(256)
gemm_tf32(const float* __restrict__ A, int lda,
          const float* __restrict__ B, int ldb,
          int M, int K,
          float* __restrict__ C, int mode,
          const float* __restrict__ inp,
          const float* __restrict__ alphaPtr) {
    extern __shared__ float sm[];

    const int tid  = threadIdx.x;
    const int wid  = tid >> 5;
    const int lane = tid & 31;
    const int l4   = lane >> 2;
    const int lm   = lane & 3;
    const int m0   = blockIdx.x * BM;
    const int wm   = (wid >> 2) * 32;   // warp m-offset (0 or 32)
    const int wn   = (wid & 3) * 64;    // warp n-offset (0,64,128,192)
    const int nk   = K / BK;

    float acc[2][8][4];
#pragma unroll
    for (int mt = 0; mt < 2; ++mt)
#pragma unroll
        for (int nt = 0; nt < 8; ++nt)
#pragma unroll
            for (int e = 0; e < 4; ++e) acc[mt][nt][e] = 0.f;

    // -------- tile loader: 1280 x 16B segments, 5 per thread --------
    auto issue_tile = [&](int c) {
        const int s = c % STAGES;
        float* dst = sm + s * STAGE_WORDS;
        const uint32_t dbase = smem_u32(dst);
        const float* gA = A + (size_t)m0 * lda + (size_t)c * BK;
        const float* gB = B + (size_t)c * BK;
#pragma unroll
        for (int t = 0; t < 5; ++t) {
            const int idx = tid + t * 256;
            const float* g;
            uint32_t soff;
            int sz = 16;
            if (idx < 256) {                       // A tile: 64 rows x 4 segs
                const int row = idx >> 2, seg = idx & 3;
                soff = (uint32_t)(row * PAD + seg * 4) * 4;
                g = gA + (size_t)row * lda + seg * 4;
                if (m0 + row >= M) { sz = 0; g = A; }
            } else {                               // B tile: 256 rows x 4 segs
                const int j = idx - 256;
                const int row = j >> 2, seg = j & 3;
                soff = (uint32_t)(A_WORDS + row * PAD + seg * 4) * 4;
                g = gB + (size_t)row * ldb + seg * 4;
            }
            cp_async16(dbase + soff, g, sz);
        }
        cp_commit();
    };

    const int npre = (nk < STAGES - 1) ? nk : (STAGES - 1);
    for (int c = 0; c < npre; ++c) issue_tile(c);

    for (int c = 0; c < nk; ++c) {
        cp_wait<STAGES - 2>();
        __syncthreads();
        if (c + STAGES - 1 < nk) issue_tile(c + STAGES - 1);
        else cp_commit();   // keep group counts aligned

        const float* sA = sm + (c % STAGES) * STAGE_WORDS;
        const float* sB = sA + A_WORDS;

#pragma unroll
        for (int ks = 0; ks < BK; ks += 8) {
            uint32_t af[2][4];
#pragma unroll
            for (int mt = 0; mt < 2; ++mt) {
                const int r = wm + mt * 16 + l4;
                af[mt][0] = f2tf32(sA[r * PAD + ks + lm]);
                af[mt][1] = f2tf32(sA[(r + 8) * PAD + ks + lm]);
                af[mt][2] = f2tf32(sA[r * PAD + ks + lm + 4]);
                af[mt][3] = f2tf32(sA[(r + 8) * PAD + ks + lm + 4]);
            }
            uint32_t bf[8][2];
#pragma unroll
            for (int nt = 0; nt < 8; ++nt) {
                const int n = wn + nt * 8 + l4;
                bf[nt][0] = __float_as_uint(sB[n * PAD + ks + lm]);
                bf[nt][1] = __float_as_uint(sB[n * PAD + ks + lm + 4]);
            }
#pragma unroll
            for (int mt = 0; mt < 2; ++mt)
#pragma unroll
                for (int nt = 0; nt < 8; ++nt)
                    mma_tf32(acc[mt][nt], af[mt], bf[nt]);
        }
    }

    // -------- epilogue --------
    const float alpha = (mode == 0) ? alphaPtr[0] : 0.f;
#pragma unroll
    for (int mt = 0; mt < 2; ++mt) {
#pragma unroll
        for (int half = 0; half < 2; ++half) {
            const int r = m0 + wm + mt * 16 + l4 + half * 8;
            if (r >= M) continue;
#pragma unroll
            for (int nt = 0; nt < 8; ++nt) {
                const int cb = wn + nt * 8 + lm * 2;
                const float v0 = acc[mt][nt][half * 2];
                const float v1 = acc[mt][nt][half * 2 + 1];
                if (mode == 0) {
                    C[(size_t)r * FF + cb]     = rnd_tf32(v0 + alpha * inp[(size_t)r * FF + cb]);
                    C[(size_t)r * FF + cb + 1] = rnd_tf32(v1 + alpha * inp[(size_t)r * FF + cb + 1]);
                } else if (mode == 1) {
                    C[(size_t)cb * NN + r]       = rnd_tf32(v0);
                    C[(size_t)(cb + 1) * NN + r] = rnd_tf32(v1);
                } else {
                    C[(size_t)r * FF + cb]     = v0;
                    C[(size_t)r * FF + cb + 1] = v1;
                }
            }
        }
    }
}

// ========================================================================
// prologue kernels
// ========================================================================
__global__ void scores_kernel(const float* __restrict__ input,
                              const float* __restrict__ attn) {
    const int gw   = (blockIdx.x * blockDim.x + threadIdx.x) >> 5;
    const int lane = threadIdx.x & 31;
    if (gw >= NN) return;
    const float* row = input + (size_t)gw * FF;
    float s = 0.f;
#pragma unroll
    for (int j = 0; j < FF / 32; ++j)
        s += row[lane + 32 * j] * __ldg(&attn[lane + 32 * j]);
#pragma unroll
    for (int o = 16; o; o >>= 1) s += __shfl_xor_sync(0xFFFFFFFFu, s, o);
    if (lane == 0) g_scores[gw] = s;
}

__global__ void softmax_kernel() {
    const int tid = threadIdx.x, lane = tid & 31, warp = tid >> 5;
    __shared__ float red[32];
    __shared__ float s_max, s_sum;
    float m = -3.4e38f;
    for (int i = tid; i < NN; i += 1024) m = fmaxf(m, g_scores[i]);
#pragma unroll
    for (int o = 16; o; o >>= 1) m = fmaxf(m, __shfl_xor_sync(0xFFFFFFFFu, m, o));
    if (lane == 0) red[warp] = m;
    __syncthreads();
    if (warp == 0) {
        m = red[lane];
#pragma unroll
        for (int o = 16; o; o >>= 1) m = fmaxf(m, __shfl_xor_sync(0xFFFFFFFFu, m, o));
        if (lane == 0) s_max = m;
    }
    __syncthreads();
    const float mx = s_max;
    float s = 0.f;
    for (int i = tid; i < NN; i += 1024) s += expf(g_scores[i] - mx);
#pragma unroll
    for (int o = 16; o; o >>= 1) s += __shfl_xor_sync(0xFFFFFFFFu, s, o);
    if (lane == 0) red[warp] = s;
    __syncthreads();
    if (warp == 0) {
        s = red[lane];
#pragma unroll
        for (int o = 16; o; o >>= 1) s += __shfl_xor_sync(0xFFFFFFFFu, s, o);
        if (lane == 0) s_sum = s;
    }
    __syncthreads();
    const float inv = 1.0f / s_sum;
    for (int i = tid; i < NN; i += 1024) g_p[i] = expf(g_scores[i] - mx) * inv;
}

// scaledT[f, i] = tf32( p[i] * input[i, f] )
__global__ void scaledT_kernel(const float* __restrict__ input) {
    __shared__ float t[32][33];
    const int tx = threadIdx.x, ty = threadIdx.y;
    const int i0 = blockIdx.x * 32, f0 = blockIdx.y * 32;
    const int i = i0 + ty, f = f0 + tx;
    t[ty][tx] = rnd_tf32(g_p[i] * input[(size_t)i * FF + f]);
    __syncthreads();
    g_scaledT[(size_t)(f0 + ty) * NN + i0 + tx] = t[tx][ty];
}

// weightT[o, i] = tf32( weight[i, o] )
__global__ void weightT_kernel(const float* __restrict__ weight) {
    __shared__ float t[32][33];
    const int tx = threadIdx.x, ty = threadIdx.y;
    const int i0 = blockIdx.x * 32, o0 = blockIdx.y * 32;
    t[ty][tx] = rnd_tf32(weight[(size_t)(i0 + ty) * FF + o0 + tx]);
    __syncthreads();
    g_weightT[(size_t)(o0 + ty) * FF + i0 + tx] = t[tx][ty];
}

// ========================================================================
// launch
// ========================================================================
extern "C" void kernel_launch(void* const* d_in, const int* in_sizes, int n_in,
                              void* d_out, int out_size) {
    const float* input  = (const float*)d_in[0];
    const float* adj    = (const float*)d_in[1];
    const float* inc    = (const float*)d_in[2];
    const float* weight = (const float*)d_in[3];
    const float* attn   = (const float*)d_in[4];
    const float* alpha  = (const float*)d_in[5];
    float* out = (float*)d_out;

    static bool configured = false;
    if (!configured) {
        cudaFuncSetAttribute(gemm_tf32,
                             cudaFuncAttributeMaxDynamicSharedMemorySize, DYN_SMEM);
        configured = true;
    }

    float *scaledT, *support4, *supportT, *weightT;
    cudaGetSymbolAddress((void**)&scaledT,  g_scaledT);
    cudaGetSymbolAddress((void**)&support4, g_support4);
    cudaGetSymbolAddress((void**)&supportT, g_supportT);
    cudaGetSymbolAddress((void**)&weightT,  g_weightT);

    scores_kernel<<<(NN + 7) / 8, 256>>>(input, attn);
    softmax_kernel<<<1, 1024>>>();
    scaledT_kernel<<<dim3(NN / 32, FF / 32), dim3(32, 32)>>>(input);
    weightT_kernel<<<dim3(FF / 32, FF / 32), dim3(32, 32)>>>(weight);

    const int grid = (NN + BM - 1) / BM;  // 188
    // GEMM1: support4 = tf32( adj @ scaled + alpha*input )
    gemm_tf32<<<grid, 256, DYN_SMEM>>>(adj, NN, scaledT, NN, NN, NN,
                                       support4, 0, input, alpha);
    // GEMM2: supportT = tf32( (support4 @ weight)^T )
    gemm_tf32<<<grid, 256, DYN_SMEM>>>(support4, FF, weightT, FF, NN, FF,
                                       supportT, 1, nullptr, nullptr);
    // GEMM3: out = incidence @ support
    gemm_tf32<<<grid, 256, DYN_SMEM>>>(inc, NN, supportT, NN, NN, NN,
                                       out, 2, nullptr, nullptr);
    (void)in_sizes; (void)n_in; (void)out_size;
}

// round 3
// speedup vs baseline: 1.5674x; 1.5674x over previous
#include <cuda_runtime.h>
#include <cstdint>
#include <math.h>

#define DEVFN static __device__ __forceinline__

// ---------------- problem constants ----------------
constexpr int NN = 12000;
constexpr int FF = 256;

// ---------------- GEMM tiling ----------------------
constexpr int BM = 128;
constexpr int BN = 256;
constexpr int BK = 16;
constexpr int STAGES = 4;
constexpr int SPLITK = 3;        // big GEMMs: K=12000 -> 3 x 250 chunks
constexpr int KCH_BIG = (NN / SPLITK) / BK;   // 250
constexpr int PAD = 20;          // floats per smem row (16 data + 4 pad)
constexpr int A_WORDS = BM * PAD;              // 2560
constexpr int B_WORDS = BN * PAD;              // 5120
constexpr int STAGE_WORDS = A_WORDS + B_WORDS; // 7680 (30720 B)
constexpr int DYN_SMEM = STAGES * STAGE_WORDS * 4;  // 122880 B

// ---------------- device scratch -------------------
__device__ float g_scores[NN];
__device__ float g_p[NN];
__device__ float g_scaledT[(size_t)FF * NN];   // [256, 12000] B for GEMM1 (tf32-rounded)
__device__ float g_support4[(size_t)NN * FF];  // [12000, 256] A for GEMM2
__device__ float g_supportT[(size_t)FF * NN];  // [256, 12000] B for GEMM3 (tf32-rounded)
__device__ float g_weightT[FF * FF];           // [256, 256]   B for GEMM2 (tf32-rounded)
__device__ float g_part[(size_t)SPLITK * NN * FF];  // split-K partials

// ---------------- PTX helpers ----------------------
DEVFN uint32_t smem_u32(const void* p) {
    uint32_t a;
    asm("{ .reg .u64 t; cvta.to.shared.u64 t, %1; cvt.u32.u64 %0, t; }" : "=r"(a) : "l"(p));
    return a;
}
DEVFN void cp_async16(uint32_t saddr, const void* gaddr, int srcsize) {
    asm volatile("cp.async.cg.shared.global [%0], [%1], 16, %2;"
                 :: "r"(saddr), "l"(gaddr), "r"(srcsize) : "memory");
}
DEVFN void cp_commit() { asm volatile("cp.async.commit_group;" ::: "memory"); }
template <int N> DEVFN void cp_wait() { asm volatile("cp.async.wait_group %0;" :: "n"(N) : "memory"); }

DEVFN uint32_t f2tf32(float x) {
    uint32_t r; asm("cvt.rna.tf32.f32 %0, %1;" : "=r"(r) : "f"(x)); return r;
}
DEVFN float rnd_tf32(float x) { return __uint_as_float(f2tf32(x)); }

DEVFN void mma_tf32(float* c, const uint32_t* a, const uint32_t* b) {
    asm volatile(
        "mma.sync.aligned.m16n8k8.row.col.f32.tf32.tf32.f32 "
        "{%0,%1,%2,%3}, {%4,%5,%6,%7}, {%8,%9}, {%0,%1,%2,%3};"
        : "+f"(c[0]), "+f"(c[1]), "+f"(c[2]), "+f"(c[3])
        : "r"(a[0]), "r"(a[1]), "r"(a[2]), "r"(a[3]), "r"(b[0]), "r"(b[1]));
}

// ========================================================================
// GEMM partial: P[r, c] = A[r, kStart:kStart+kn*BK] @ B[c, same]^T
//   A fragments rounded to tf32 (rna) in-kernel; B assumed pre-rounded.
//   grid = (ceil(M/BM), nSplit); blockIdx.y selects K-slab and partial slab.
// ========================================================================
__global__ void __launch_bounds__(512, 1)
gemm_tf32(const float* __restrict__ A, int lda,
          const float* __restrict__ B, int ldb,
          int M, int kChunks,
          float* __restrict__ P) {
    extern __shared__ float sm[];

    const int tid  = threadIdx.x;
    const int wid  = tid >> 5;
    const int lane = tid & 31;
    const int l4   = lane >> 2;
    const int lm   = lane & 3;
    const int m0   = blockIdx.x * BM;
    const int wm   = (wid >> 2) * 32;   // 0,32,64,96
    const int wn   = (wid & 3) * 64;    // 0,64,128,192
    const size_t kStart = (size_t)blockIdx.y * kChunks * BK;
    float* __restrict__ Pp = P + (size_t)blockIdx.y * NN * FF;

    float acc[2][8][4];
#pragma unroll
    for (int mt = 0; mt < 2; ++mt)
#pragma unroll
        for (int nt = 0; nt < 8; ++nt)
#pragma unroll
            for (int e = 0; e < 4; ++e) acc[mt][nt][e] = 0.f;

    // -------- tile loader: 1536 x 16B segments, 3 per thread --------
    auto issue_tile = [&](int c) {
        const int s = c & (STAGES - 1);
        const uint32_t dbase = smem_u32(sm + s * STAGE_WORDS);
        const float* gA = A + (size_t)m0 * lda + kStart + (size_t)c * BK;
        const float* gB = B + kStart + (size_t)c * BK;
#pragma unroll
        for (int t = 0; t < 3; ++t) {
            const int idx = tid + t * 512;
            const float* g;
            uint32_t soff;
            int sz = 16;
            if (idx < 512) {                       // A tile: 128 rows x 4 segs
                const int row = idx >> 2, seg = idx & 3;
                soff = (uint32_t)(row * PAD + seg * 4) * 4;
                g = gA + (size_t)row * lda + seg * 4;
                if (m0 + row >= M) { sz = 0; g = A; }
            } else {                               // B tile: 256 rows x 4 segs
                const int j = idx - 512;
                const int row = j >> 2, seg = j & 3;
                soff = (uint32_t)(A_WORDS + row * PAD + seg * 4) * 4;
                g = gB + (size_t)row * ldb + seg * 4;
            }
            cp_async16(dbase + soff, g, sz);
        }
        cp_commit();
    };

    const int npre = (kChunks < STAGES - 1) ? kChunks : (STAGES - 1);
    for (int c = 0; c < npre; ++c) issue_tile(c);

    for (int c = 0; c < kChunks; ++c) {
        cp_wait<STAGES - 2>();
        __syncthreads();
        if (c + STAGES - 1 < kChunks) issue_tile(c + STAGES - 1);
        else cp_commit();   // keep group counts aligned

        const float* sA = sm + (c & (STAGES - 1)) * STAGE_WORDS;
        const float* sB = sA + A_WORDS;

#pragma unroll
        for (int ks = 0; ks < BK; ks += 8) {
            uint32_t af[2][4];
#pragma unroll
            for (int mt = 0; mt < 2; ++mt) {
                const int r = wm + mt * 16 + l4;
                af[mt][0] = f2tf32(sA[r * PAD + ks + lm]);
                af[mt][1] = f2tf32(sA[(r + 8) * PAD + ks + lm]);
                af[mt][2] = f2tf32(sA[r * PAD + ks + lm + 4]);
                af[mt][3] = f2tf32(sA[(r + 8) * PAD + ks + lm + 4]);
            }
            uint32_t bf[8][2];
#pragma unroll
            for (int nt = 0; nt < 8; ++nt) {
                const int n = wn + nt * 8 + l4;
                bf[nt][0] = __float_as_uint(sB[n * PAD + ks + lm]);
                bf[nt][1] = __float_as_uint(sB[n * PAD + ks + lm + 4]);
            }
#pragma unroll
            for (int mt = 0; mt < 2; ++mt)
#pragma unroll
                for (int nt = 0; nt < 8; ++nt)
                    mma_tf32(acc[mt][nt], af[mt], bf[nt]);
        }
    }

    // -------- epilogue: raw partial stores (float2) --------
#pragma unroll
    for (int mt = 0; mt < 2; ++mt) {
#pragma unroll
        for (int half = 0; half < 2; ++half) {
            const int r = m0 + wm + mt * 16 + l4 + half * 8;
            if (r >= M) continue;
#pragma unroll
            for (int nt = 0; nt < 8; ++nt) {
                const int cb = wn + nt * 8 + lm * 2;
                float2 v = make_float2(acc[mt][nt][half * 2], acc[mt][nt][half * 2 + 1]);
                *reinterpret_cast<float2*>(&Pp[(size_t)r * FF + cb]) = v;
            }
        }
    }
}

// ========================================================================
// reduction / epilogue kernels
// ========================================================================
// support4 = sum(partials) + alpha*input     (fp32; A-op of GEMM2, cvt'd there)
__global__ void reduce_alpha_kernel(const float* __restrict__ inp,
                                    const float* __restrict__ alphaPtr) {
    const size_t i = ((size_t)blockIdx.x * blockDim.x + threadIdx.x) * 4;
    const float alpha = alphaPtr[0];
    float4 p0 = *reinterpret_cast<const float4*>(&g_part[i]);
    float4 p1 = *reinterpret_cast<const float4*>(&g_part[(size_t)NN * FF + i]);
    float4 p2 = *reinterpret_cast<const float4*>(&g_part[(size_t)2 * NN * FF + i]);
    float4 x  = *reinterpret_cast<const float4*>(&inp[i]);
    float4 r;
    r.x = p0.x + p1.x + p2.x + alpha * x.x;
    r.y = p0.y + p1.y + p2.y + alpha * x.y;
    r.z = p0.z + p1.z + p2.z + alpha * x.z;
    r.w = p0.w + p1.w + p2.w + alpha * x.w;
    *reinterpret_cast<float4*>(&g_support4[i]) = r;
}

// out = sum(partials)   (final fp32 output)
__global__ void reduce_sum_kernel(float* __restrict__ out) {
    const size_t i = ((size_t)blockIdx.x * blockDim.x + threadIdx.x) * 4;
    float4 p0 = *reinterpret_cast<const float4*>(&g_part[i]);
    float4 p1 = *reinterpret_cast<const float4*>(&g_part[(size_t)NN * FF + i]);
    float4 p2 = *reinterpret_cast<const float4*>(&g_part[(size_t)2 * NN * FF + i]);
    float4 r;
    r.x = p0.x + p1.x + p2.x;
    r.y = p0.y + p1.y + p2.y;
    r.z = p0.z + p1.z + p2.z;
    r.w = p0.w + p1.w + p2.w;
    *reinterpret_cast<float4*>(&out[i]) = r;
}

// supportT[c*NN + r] = tf32( part0[r*FF + c] )   (B-op of GEMM3: pre-rounded)
__global__ void transT_kernel() {
    __shared__ float t[32][33];
    const int tx = threadIdx.x, ty = threadIdx.y;
    const int r0 = blockIdx.x * 32, c0 = blockIdx.y * 32;
    t[ty][tx] = rnd_tf32(g_part[(size_t)(r0 + ty) * FF + c0 + tx]);
    __syncthreads();
    g_supportT[(size_t)(c0 + ty) * NN + r0 + tx] = t[tx][ty];
}

// ========================================================================
// prologue kernels
// ========================================================================
__global__ void scores_kernel(const float* __restrict__ input,
                              const float* __restrict__ attn) {
    const int gw   = (blockIdx.x * blockDim.x + threadIdx.x) >> 5;
    const int lane = threadIdx.x & 31;
    if (gw >= NN) return;
    const float* row = input + (size_t)gw * FF;
    float s = 0.f;
#pragma unroll
    for (int j = 0; j < FF / 32; ++j)
        s += row[lane + 32 * j] * __ldg(&attn[lane + 32 * j]);
#pragma unroll
    for (int o = 16; o; o >>= 1) s += __shfl_xor_sync(0xFFFFFFFFu, s, o);
    if (lane == 0) g_scores[gw] = s;
}

__global__ void softmax_kernel() {
    const int tid = threadIdx.x, lane = tid & 31, warp = tid >> 5;
    __shared__ float red[32];
    __shared__ float s_max, s_sum;
    float m = -3.4e38f;
    for (int i = tid; i < NN; i += 1024) m = fmaxf(m, g_scores[i]);
#pragma unroll
    for (int o = 16; o; o >>= 1) m = fmaxf(m, __shfl_xor_sync(0xFFFFFFFFu, m, o));
    if (lane == 0) red[warp] = m;
    __syncthreads();
    if (warp == 0) {
        m = red[lane];
#pragma unroll
        for (int o = 16; o; o >>= 1) m = fmaxf(m, __shfl_xor_sync(0xFFFFFFFFu, m, o));
        if (lane == 0) s_max = m;
    }
    __syncthreads();
    const float mx = s_max;
    float s = 0.f;
    for (int i = tid; i < NN; i += 1024) s += expf(g_scores[i] - mx);
#pragma unroll
    for (int o = 16; o; o >>= 1) s += __shfl_xor_sync(0xFFFFFFFFu, s, o);
    if (lane == 0) red[warp] = s;
    __syncthreads();
    if (warp == 0) {
        s = red[lane];
#pragma unroll
        for (int o = 16; o; o >>= 1) s += __shfl_xor_sync(0xFFFFFFFFu, s, o);
        if (lane == 0) s_sum = s;
    }
    __syncthreads();
    const float inv = 1.0f / s_sum;
    for (int i = tid; i < NN; i += 1024) g_p[i] = expf(g_scores[i] - mx) * inv;
}

// scaledT[f, i] = tf32( p[i] * input[i, f] )
__global__ void scaledT_kernel(const float* __restrict__ input) {
    __shared__ float t[32][33];
    const int tx = threadIdx.x, ty = threadIdx.y;
    const int i0 = blockIdx.x * 32, f0 = blockIdx.y * 32;
    const int i = i0 + ty, f = f0 + tx;
    t[ty][tx] = rnd_tf32(g_p[i] * input[(size_t)i * FF + f]);
    __syncthreads();
    g_scaledT[(size_t)(f0 + ty) * NN + i0 + tx] = t[tx][ty];
}

// weightT[o, i] = tf32( weight[i, o] )
__global__ void weightT_kernel(const float* __restrict__ weight) {
    __shared__ float t[32][33];
    const int tx = threadIdx.x, ty = threadIdx.y;
    const int i0 = blockIdx.x * 32, o0 = blockIdx.y * 32;
    t[ty][tx] = rnd_tf32(weight[(size_t)(i0 + ty) * FF + o0 + tx]);
    __syncthreads();
    g_weightT[(size_t)(o0 + ty) * FF + i0 + tx] = t[tx][ty];
}

// ========================================================================
// launch
// ========================================================================
extern "C" void kernel_launch(void* const* d_in, const int* in_sizes, int n_in,
                              void* d_out, int out_size) {
    const float* input  = (const float*)d_in[0];
    const float* adj    = (const float*)d_in[1];
    const float* inc    = (const float*)d_in[2];
    const float* weight = (const float*)d_in[3];
    const float* attn   = (const float*)d_in[4];
    const float* alpha  = (const float*)d_in[5];
    float* out = (float*)d_out;

    cudaFuncSetAttribute(gemm_tf32,
                         cudaFuncAttributeMaxDynamicSharedMemorySize, DYN_SMEM);

    float *scaledT, *support4, *supportT, *weightT, *part;
    cudaGetSymbolAddress((void**)&scaledT,  g_scaledT);
    cudaGetSymbolAddress((void**)&support4, g_support4);
    cudaGetSymbolAddress((void**)&supportT, g_supportT);
    cudaGetSymbolAddress((void**)&weightT,  g_weightT);
    cudaGetSymbolAddress((void**)&part,     g_part);

    scores_kernel<<<(NN + 7) / 8, 256>>>(input, attn);
    softmax_kernel<<<1, 1024>>>();
    scaledT_kernel<<<dim3(NN / 32, FF / 32), dim3(32, 32)>>>(input);
    weightT_kernel<<<dim3(FF / 32, FF / 32), dim3(32, 32)>>>(weight);

    const int gridM = (NN + BM - 1) / BM;  // 94
    const int redBlocks = (NN * FF / 4) / 1024;  // 750

    // GEMM1: partials of adj @ scaled  (split-K=3)
    gemm_tf32<<<dim3(gridM, SPLITK), 512, DYN_SMEM>>>(adj, NN, scaledT, NN,
                                                      NN, KCH_BIG, part);
    // support4 = sum + alpha*input
    reduce_alpha_kernel<<<redBlocks, 1024>>>(input, alpha);

    // GEMM2: part0 = support4 @ weight  (K=256, no split)
    gemm_tf32<<<dim3(gridM, 1), 512, DYN_SMEM>>>(support4, FF, weightT, FF,
                                                 NN, FF / BK, part);
    // supportT = tf32(part0)^T
    transT_kernel<<<dim3(NN / 32, FF / 32), dim3(32, 32)>>>();

    // GEMM3: partials of incidence @ support  (split-K=3)
    gemm_tf32<<<dim3(gridM, SPLITK), 512, DYN_SMEM>>>(inc, NN, supportT, NN,
                                                      NN, KCH_BIG, part);
    // out = sum
    reduce_sum_kernel<<<redBlocks, 1024>>>(out);

    (void)in_sizes; (void)n_in; (void)out_size;
}

// round 4
// speedup vs baseline: 1.8857x; 1.2031x over previous
#include <cuda_runtime.h>
#include <cuda_bf16.h>
#include <cstdint>
#include <math.h>

#define DEVFN static __device__ __forceinline__

// ---------------- problem constants ----------------
constexpr int NN = 12000;
constexpr int FF = 256;

// ---------------- shared GEMM config ----------------
constexpr int BM = 128;
constexpr int BN = 256;
constexpr int SPLITK = 3;

// ----- tf32 kernel tiling (GEMM2 / GEMM3) -----
constexpr int BK = 16;
constexpr int STAGES = 4;
constexpr int PAD = 20;
constexpr int A_WORDS = BM * PAD;               // 2560
constexpr int B_WORDS = BN * PAD;               // 5120
constexpr int STAGE_WORDS = A_WORDS + B_WORDS;  // 7680
constexpr int DYN_SMEM = STAGES * STAGE_WORDS * 4;   // 122880
constexpr int KCH_BIG = (NN / SPLITK) / BK;     // 250

// ----- bf16 kernel tiling (GEMM1) -----
constexpr int BK2 = 32;
constexpr int STAGES2 = 4;
constexpr int PADA2 = 36;                        // fp32 words per A row
constexpr int PADB2 = 40;                        // bf16 elems per B row
constexpr int A_BYTES2 = BM * PADA2 * 4;         // 18432
constexpr int B_BYTES2 = BN * PADB2 * 2;         // 20480
constexpr int STAGE_BYTES2 = A_BYTES2 + B_BYTES2; // 38912
constexpr int DYN_SMEM2 = STAGES2 * STAGE_BYTES2; // 155648
constexpr int KCH_BIG2 = (NN / SPLITK) / BK2;    // 125

// ---------------- device scratch -------------------
__device__ float g_scores[NN];
__device__ float g_p[NN];
__device__ __nv_bfloat16 g_scaledT16[(size_t)FF * NN]; // [256,12000] B for GEMM1 (bf16)
__device__ float g_support4[(size_t)NN * FF];  // A for GEMM2
__device__ float g_supportT[(size_t)FF * NN];  // B for GEMM3 (tf32-rounded)
__device__ float g_weightT[FF * FF];           // B for GEMM2 (tf32-rounded)
__device__ float g_part[(size_t)SPLITK * NN * FF];  // split-K partials

// ---------------- PTX helpers ----------------------
DEVFN uint32_t smem_u32(const void* p) {
    uint32_t a;
    asm("{ .reg .u64 t; cvta.to.shared.u64 t, %1; cvt.u32.u64 %0, t; }" : "=r"(a) : "l"(p));
    return a;
}
DEVFN void cp_async16(uint32_t saddr, const void* gaddr, int srcsize) {
    asm volatile("cp.async.cg.shared.global [%0], [%1], 16, %2;"
                 :: "r"(saddr), "l"(gaddr), "r"(srcsize) : "memory");
}
DEVFN void cp_commit() { asm volatile("cp.async.commit_group;" ::: "memory"); }
template <int N> DEVFN void cp_wait() { asm volatile("cp.async.wait_group %0;" :: "n"(N) : "memory"); }

DEVFN uint32_t f2tf32(float x) {
    uint32_t r; asm("cvt.rna.tf32.f32 %0, %1;" : "=r"(r) : "f"(x)); return r;
}
DEVFN float rnd_tf32(float x) { return __uint_as_float(f2tf32(x)); }

DEVFN void mma_tf32(float* c, const uint32_t* a, const uint32_t* b) {
    asm volatile(
        "mma.sync.aligned.m16n8k8.row.col.f32.tf32.tf32.f32 "
        "{%0,%1,%2,%3}, {%4,%5,%6,%7}, {%8,%9}, {%0,%1,%2,%3};"
        : "+f"(c[0]), "+f"(c[1]), "+f"(c[2]), "+f"(c[3])
        : "r"(a[0]), "r"(a[1]), "r"(a[2]), "r"(a[3]), "r"(b[0]), "r"(b[1]));
}
DEVFN void mma_bf16(float* c, const uint32_t* a, const uint32_t* b) {
    asm volatile(
        "mma.sync.aligned.m16n8k16.row.col.f32.bf16.bf16.f32 "
        "{%0,%1,%2,%3}, {%4,%5,%6,%7}, {%8,%9}, {%0,%1,%2,%3};"
        : "+f"(c[0]), "+f"(c[1]), "+f"(c[2]), "+f"(c[3])
        : "r"(a[0]), "r"(a[1]), "r"(a[2]), "r"(a[3]), "r"(b[0]), "r"(b[1]));
}
DEVFN uint32_t pack_bf16x2(float lo, float hi) {
    __nv_bfloat162 h = __float22bfloat162_rn(make_float2(lo, hi));
    return *reinterpret_cast<uint32_t*>(&h);
}

// ========================================================================
// tf32 GEMM partial: P[r,c] = A[r, kSlab] @ B[c, kSlab]^T
// ========================================================================
__global__ void __launch_bounds__(512, 1)
gemm_tf32(const float* __restrict__ A, int lda,
          const float* __restrict__ B, int ldb,
          int M, int kChunks,
          float* __restrict__ P) {
    extern __shared__ float sm[];

    const int tid  = threadIdx.x;
    const int wid  = tid >> 5;
    const int lane = tid & 31;
    const int l4   = lane >> 2;
    const int lm   = lane & 3;
    const int m0   = blockIdx.x * BM;
    const int wm   = (wid >> 2) * 32;
    const int wn   = (wid & 3) * 64;
    const size_t kStart = (size_t)blockIdx.y * kChunks * BK;
    float* __restrict__ Pp = P + (size_t)blockIdx.y * NN * FF;

    float acc[2][8][4];
#pragma unroll
    for (int mt = 0; mt < 2; ++mt)
#pragma unroll
        for (int nt = 0; nt < 8; ++nt)
#pragma unroll
            for (int e = 0; e < 4; ++e) acc[mt][nt][e] = 0.f;

    auto issue_tile = [&](int c) {
        const int s = c & (STAGES - 1);
        const uint32_t dbase = smem_u32(sm + s * STAGE_WORDS);
        const float* gA = A + (size_t)m0 * lda + kStart + (size_t)c * BK;
        const float* gB = B + kStart + (size_t)c * BK;
#pragma unroll
        for (int t = 0; t < 3; ++t) {
            const int idx = tid + t * 512;
            const float* g;
            uint32_t soff;
            int sz = 16;
            if (idx < 512) {
                const int row = idx >> 2, seg = idx & 3;
                soff = (uint32_t)(row * PAD + seg * 4) * 4;
                g = gA + (size_t)row * lda + seg * 4;
                if (m0 + row >= M) { sz = 0; g = A; }
            } else {
                const int j = idx - 512;
                const int row = j >> 2, seg = j & 3;
                soff = (uint32_t)(A_WORDS + row * PAD + seg * 4) * 4;
                g = gB + (size_t)row * ldb + seg * 4;
            }
            cp_async16(dbase + soff, g, sz);
        }
        cp_commit();
    };

    const int npre = (kChunks < STAGES - 1) ? kChunks : (STAGES - 1);
    for (int c = 0; c < npre; ++c) issue_tile(c);

    for (int c = 0; c < kChunks; ++c) {
        cp_wait<STAGES - 2>();
        __syncthreads();
        if (c + STAGES - 1 < kChunks) issue_tile(c + STAGES - 1);
        else cp_commit();

        const float* sA = sm + (c & (STAGES - 1)) * STAGE_WORDS;
        const float* sB = sA + A_WORDS;

#pragma unroll
        for (int ks = 0; ks < BK; ks += 8) {
            uint32_t af[2][4];
#pragma unroll
            for (int mt = 0; mt < 2; ++mt) {
                const int r = wm + mt * 16 + l4;
                af[mt][0] = f2tf32(sA[r * PAD + ks + lm]);
                af[mt][1] = f2tf32(sA[(r + 8) * PAD + ks + lm]);
                af[mt][2] = f2tf32(sA[r * PAD + ks + lm + 4]);
                af[mt][3] = f2tf32(sA[(r + 8) * PAD + ks + lm + 4]);
            }
            uint32_t bf[8][2];
#pragma unroll
            for (int nt = 0; nt < 8; ++nt) {
                const int n = wn + nt * 8 + l4;
                bf[nt][0] = __float_as_uint(sB[n * PAD + ks + lm]);
                bf[nt][1] = __float_as_uint(sB[n * PAD + ks + lm + 4]);
            }
#pragma unroll
            for (int mt = 0; mt < 2; ++mt)
#pragma unroll
                for (int nt = 0; nt < 8; ++nt)
                    mma_tf32(acc[mt][nt], af[mt], bf[nt]);
        }
    }

#pragma unroll
    for (int mt = 0; mt < 2; ++mt) {
#pragma unroll
        for (int half = 0; half < 2; ++half) {
            const int r = m0 + wm + mt * 16 + l4 + half * 8;
            if (r >= M) continue;
#pragma unroll
            for (int nt = 0; nt < 8; ++nt) {
                const int cb = wn + nt * 8 + lm * 2;
                float2 v = make_float2(acc[mt][nt][half * 2], acc[mt][nt][half * 2 + 1]);
                *reinterpret_cast<float2*>(&Pp[(size_t)r * FF + cb]) = v;
            }
        }
    }
}

// ========================================================================
// bf16 GEMM partial (GEMM1): P[r,c] = bf16(A[r,kSlab]) @ B16[c,kSlab]^T
//   A fp32 in smem, converted to bf16 per-fragment; B16 pre-converted bf16.
// ========================================================================
__global__ void __launch_bounds__(512, 1)
gemm_bf16(const float* __restrict__ A, int lda,
          const __nv_bfloat16* __restrict__ B16, int ldb,
          int M, int kChunks,
          float* __restrict__ P) {
    extern __shared__ char sm2[];

    const int tid  = threadIdx.x;
    const int wid  = tid >> 5;
    const int lane = tid & 31;
    const int l4   = lane >> 2;
    const int lm   = lane & 3;
    const int m0   = blockIdx.x * BM;
    const int wm   = (wid >> 2) * 32;
    const int wn   = (wid & 3) * 64;
    const size_t kStart = (size_t)blockIdx.y * kChunks * BK2;
    float* __restrict__ Pp = P + (size_t)blockIdx.y * NN * FF;

    float acc[2][8][4];
#pragma unroll
    for (int mt = 0; mt < 2; ++mt)
#pragma unroll
        for (int nt = 0; nt < 8; ++nt)
#pragma unroll
            for (int e = 0; e < 4; ++e) acc[mt][nt][e] = 0.f;

    // 2048 x 16B segments per stage, 4 per thread
    auto issue_tile = [&](int c) {
        const int s = c & (STAGES2 - 1);
        const uint32_t dbase = smem_u32(sm2 + s * STAGE_BYTES2);
        const float* gA = A + (size_t)m0 * lda + kStart + (size_t)c * BK2;
        const __nv_bfloat16* gB = B16 + kStart + (size_t)c * BK2;
#pragma unroll
        for (int t = 0; t < 4; ++t) {
            const int idx = tid + t * 512;
            const void* g;
            uint32_t soff;
            int sz = 16;
            if (idx < 1024) {                  // A: 128 rows x 8 segs (fp32)
                const int row = idx >> 3, seg = idx & 7;
                soff = (uint32_t)(row * PADA2 + seg * 4) * 4;
                g = gA + (size_t)row * lda + seg * 4;
                if (m0 + row >= M) { sz = 0; g = A; }
            } else {                           // B: 256 rows x 4 segs (bf16)
                const int j = idx - 1024;
                const int row = j >> 2, seg = j & 3;
                soff = A_BYTES2 + (uint32_t)(row * PADB2 + seg * 8) * 2;
                g = gB + (size_t)row * ldb + seg * 8;
            }
            cp_async16(dbase + soff, g, sz);
        }
        cp_commit();
    };

    const int npre = (kChunks < STAGES2 - 1) ? kChunks : (STAGES2 - 1);
    for (int c = 0; c < npre; ++c) issue_tile(c);

    for (int c = 0; c < kChunks; ++c) {
        cp_wait<STAGES2 - 2>();
        __syncthreads();
        if (c + STAGES2 - 1 < kChunks) issue_tile(c + STAGES2 - 1);
        else cp_commit();

        const char* stage = sm2 + (c & (STAGES2 - 1)) * STAGE_BYTES2;
        const float* sA = reinterpret_cast<const float*>(stage);
        const uint32_t* sB = reinterpret_cast<const uint32_t*>(stage + A_BYTES2); // bf16x2 words

#pragma unroll
        for (int ks = 0; ks < BK2; ks += 16) {
            uint32_t af[2][4];
#pragma unroll
            for (int mt = 0; mt < 2; ++mt) {
                const int r0 = wm + mt * 16 + l4;
                const float* pr0 = sA + r0 * PADA2 + ks + 2 * lm;
                const float* pr1 = sA + (r0 + 8) * PADA2 + ks + 2 * lm;
                float2 x0 = *reinterpret_cast<const float2*>(pr0);      // k even,odd
                float2 x1 = *reinterpret_cast<const float2*>(pr1);
                float2 x2 = *reinterpret_cast<const float2*>(pr0 + 8);
                float2 x3 = *reinterpret_cast<const float2*>(pr1 + 8);
                af[mt][0] = pack_bf16x2(x0.x, x0.y);
                af[mt][1] = pack_bf16x2(x1.x, x1.y);
                af[mt][2] = pack_bf16x2(x2.x, x2.y);
                af[mt][3] = pack_bf16x2(x3.x, x3.y);
            }
            uint32_t bf[8][2];
#pragma unroll
            for (int nt = 0; nt < 8; ++nt) {
                const int n = wn + nt * 8 + l4;
                const int base = (n * PADB2 + ks + 2 * lm) >> 1;  // bf16x2 word index
                bf[nt][0] = sB[base];
                bf[nt][1] = sB[base + 4];
            }
#pragma unroll
            for (int mt = 0; mt < 2; ++mt)
#pragma unroll
                for (int nt = 0; nt < 8; ++nt)
                    mma_bf16(acc[mt][nt], af[mt], bf[nt]);
        }
    }

#pragma unroll
    for (int mt = 0; mt < 2; ++mt) {
#pragma unroll
        for (int half = 0; half < 2; ++half) {
            const int r = m0 + wm + mt * 16 + l4 + half * 8;
            if (r >= M) continue;
#pragma unroll
            for (int nt = 0; nt < 8; ++nt) {
                const int cb = wn + nt * 8 + lm * 2;
                float2 v = make_float2(acc[mt][nt][half * 2], acc[mt][nt][half * 2 + 1]);
                *reinterpret_cast<float2*>(&Pp[(size_t)r * FF + cb]) = v;
            }
        }
    }
}

// ========================================================================
// reduction / epilogue kernels
// ========================================================================
__global__ void reduce_alpha_kernel(const float* __restrict__ inp,
                                    const float* __restrict__ alphaPtr) {
    const size_t i = ((size_t)blockIdx.x * blockDim.x + threadIdx.x) * 4;
    const float alpha = alphaPtr[0];
    float4 p0 = *reinterpret_cast<const float4*>(&g_part[i]);
    float4 p1 = *reinterpret_cast<const float4*>(&g_part[(size_t)NN * FF + i]);
    float4 p2 = *reinterpret_cast<const float4*>(&g_part[(size_t)2 * NN * FF + i]);
    float4 x  = *reinterpret_cast<const float4*>(&inp[i]);
    float4 r;
    r.x = p0.x + p1.x + p2.x + alpha * x.x;
    r.y = p0.y + p1.y + p2.y + alpha * x.y;
    r.z = p0.z + p1.z + p2.z + alpha * x.z;
    r.w = p0.w + p1.w + p2.w + alpha * x.w;
    *reinterpret_cast<float4*>(&g_support4[i]) = r;
}

__global__ void reduce_sum_kernel(float* __restrict__ out) {
    const size_t i = ((size_t)blockIdx.x * blockDim.x + threadIdx.x) * 4;
    float4 p0 = *reinterpret_cast<const float4*>(&g_part[i]);
    float4 p1 = *reinterpret_cast<const float4*>(&g_part[(size_t)NN * FF + i]);
    float4 p2 = *reinterpret_cast<const float4*>(&g_part[(size_t)2 * NN * FF + i]);
    float4 r;
    r.x = p0.x + p1.x + p2.x;
    r.y = p0.y + p1.y + p2.y;
    r.z = p0.z + p1.z + p2.z;
    r.w = p0.w + p1.w + p2.w;
    *reinterpret_cast<float4*>(&out[i]) = r;
}

// supportT[c*NN + r] = tf32( part0[r*FF + c] )
__global__ void transT_kernel() {
    __shared__ float t[32][33];
    const int tx = threadIdx.x, ty = threadIdx.y;
    const int r0 = blockIdx.x * 32, c0 = blockIdx.y * 32;
    t[ty][tx] = rnd_tf32(g_part[(size_t)(r0 + ty) * FF + c0 + tx]);
    __syncthreads();
    g_supportT[(size_t)(c0 + ty) * NN + r0 + tx] = t[tx][ty];
}

// ========================================================================
// prologue kernels
// ========================================================================
__global__ void scores_kernel(const float* __restrict__ input,
                              const float* __restrict__ attn) {
    const int gw   = (blockIdx.x * blockDim.x + threadIdx.x) >> 5;
    const int lane = threadIdx.x & 31;
    if (gw >= NN) return;
    const float* row = input + (size_t)gw * FF;
    float s = 0.f;
#pragma unroll
    for (int j = 0; j < FF / 32; ++j)
        s += row[lane + 32 * j] * __ldg(&attn[lane + 32 * j]);
#pragma unroll
    for (int o = 16; o; o >>= 1) s += __shfl_xor_sync(0xFFFFFFFFu, s, o);
    if (lane == 0) g_scores[gw] = s;
}

__global__ void softmax_kernel() {
    const int tid = threadIdx.x, lane = tid & 31, warp = tid >> 5;
    __shared__ float red[32];
    __shared__ float s_max, s_sum;
    float m = -3.4e38f;
    for (int i = tid; i < NN; i += 1024) m = fmaxf(m, g_scores[i]);
#pragma unroll
    for (int o = 16; o; o >>= 1) m = fmaxf(m, __shfl_xor_sync(0xFFFFFFFFu, m, o));
    if (lane == 0) red[warp] = m;
    __syncthreads();
    if (warp == 0) {
        m = red[lane];
#pragma unroll
        for (int o = 16; o; o >>= 1) m = fmaxf(m, __shfl_xor_sync(0xFFFFFFFFu, m, o));
        if (lane == 0) s_max = m;
    }
    __syncthreads();
    const float mx = s_max;
    float s = 0.f;
    for (int i = tid; i < NN; i += 1024) s += expf(g_scores[i] - mx);
#pragma unroll
    for (int o = 16; o; o >>= 1) s += __shfl_xor_sync(0xFFFFFFFFu, s, o);
    if (lane == 0) red[warp] = s;
    __syncthreads();
    if (warp == 0) {
        s = red[lane];
#pragma unroll
        for (int o = 16; o; o >>= 1) s += __shfl_xor_sync(0xFFFFFFFFu, s, o);
        if (lane == 0) s_sum = s;
    }
    __syncthreads();
    const float inv = 1.0f / s_sum;
    for (int i = tid; i < NN; i += 1024) g_p[i] = expf(g_scores[i] - mx) * inv;
}

// scaledT16[f, i] = bf16( p[i] * input[i, f] )
__global__ void scaledT_kernel(const float* __restrict__ input) {
    __shared__ float t[32][33];
    const int tx = threadIdx.x, ty = threadIdx.y;
    const int i0 = blockIdx.x * 32, f0 = blockIdx.y * 32;
    const int i = i0 + ty, f = f0 + tx;
    t[ty][tx] = g_p[i] * input[(size_t)i * FF + f];
    __syncthreads();
    g_scaledT16[(size_t)(f0 + ty) * NN + i0 + tx] = __float2bfloat16_rn(t[tx][ty]);
}

// weightT[o, i] = tf32( weight[i, o] )
__global__ void weightT_kernel(const float* __restrict__ weight) {
    __shared__ float t[32][33];
    const int tx = threadIdx.x, ty = threadIdx.y;
    const int i0 = blockIdx.x * 32, o0 = blockIdx.y * 32;
    t[ty][tx] = rnd_tf32(weight[(size_t)(i0 + ty) * FF + o0 + tx]);
    __syncthreads();
    g_weightT[(size_t)(o0 + ty) * FF + i0 + tx] = t[tx][ty];
}

// ========================================================================
// launch
// ========================================================================
extern "C" void kernel_launch(void* const* d_in, const int* in_sizes, int n_in,
                              void* d_out, int out_size) {
    const float* input  = (const float*)d_in[0];
    const float* adj    = (const float*)d_in[1];
    const float* inc    = (const float*)d_in[2];
    const float* weight = (const float*)d_in[3];
    const float* attn   = (const float*)d_in[4];
    const float* alpha  = (const float*)d_in[5];
    float* out = (float*)d_out;

    cudaFuncSetAttribute(gemm_tf32,
                         cudaFuncAttributeMaxDynamicSharedMemorySize, DYN_SMEM);
    cudaFuncSetAttribute(gemm_bf16,
                         cudaFuncAttributeMaxDynamicSharedMemorySize, DYN_SMEM2);

    __nv_bfloat16* scaledT16;
    float *support4, *supportT, *weightT, *part;
    cudaGetSymbolAddress((void**)&scaledT16, g_scaledT16);
    cudaGetSymbolAddress((void**)&support4,  g_support4);
    cudaGetSymbolAddress((void**)&supportT,  g_supportT);
    cudaGetSymbolAddress((void**)&weightT,   g_weightT);
    cudaGetSymbolAddress((void**)&part,      g_part);

    scores_kernel<<<(NN + 7) / 8, 256>>>(input, attn);
    softmax_kernel<<<1, 1024>>>();
    scaledT_kernel<<<dim3(NN / 32, FF / 32), dim3(32, 32)>>>(input);
    weightT_kernel<<<dim3(FF / 32, FF / 32), dim3(32, 32)>>>(weight);

    const int gridM = (NN + BM - 1) / BM;        // 94
    const int redBlocks = (NN * FF / 4) / 1024;  // 750

    // GEMM1 (bf16): partials of adj @ scaled  (split-K=3)
    gemm_bf16<<<dim3(gridM, SPLITK), 512, DYN_SMEM2>>>(adj, NN, scaledT16, NN,
                                                       NN, KCH_BIG2, part);
    reduce_alpha_kernel<<<redBlocks, 1024>>>(input, alpha);

    // GEMM2 (tf32): part0 = support4 @ weight
    gemm_tf32<<<dim3(gridM, 1), 512, DYN_SMEM>>>(support4, FF, weightT, FF,
                                                 NN, FF / BK, part);
    transT_kernel<<<dim3(NN / 32, FF / 32), dim3(32, 32)>>>();

    // GEMM3 (tf32): partials of incidence @ support  (split-K=3)
    gemm_tf32<<<dim3(gridM, SPLITK), 512, DYN_SMEM>>>(inc, NN, supportT, NN,
                                                      NN, KCH_BIG, part);
    reduce_sum_kernel<<<redBlocks, 1024>>>(out);

    (void)in_sizes; (void)n_in; (void)out_size;
}

// round 6
// speedup vs baseline: 2.3777x; 1.2609x over previous
#include <cuda_runtime.h>
#include <cuda_bf16.h>
#include <cuda_fp16.h>
#include <cstdint>
#include <math.h>

#define DEVFN static __device__ __forceinline__

// ---------------- problem constants ----------------
constexpr int NN = 12000;
constexpr int FF = 256;

// ---------------- shared GEMM config ----------------
constexpr int BM = 128;
constexpr int BN = 256;
constexpr int SPLITK = 3;

// ----- tf32 kernel tiling (GEMM2) -----
constexpr int BK = 16;
constexpr int STAGES = 4;
constexpr int PAD = 20;
constexpr int A_WORDS = BM * PAD;               // 2560
constexpr int B_WORDS = BN * PAD;               // 5120
constexpr int STAGE_WORDS = A_WORDS + B_WORDS;  // 7680
constexpr int DYN_SMEM = STAGES * STAGE_WORDS * 4;   // 122880

// ----- 16-bit kernel tiling (GEMM1 bf16 / GEMM3 fp16) -----
constexpr int BK2 = 32;
constexpr int STAGES2 = 4;
constexpr int PADA2 = 36;                        // fp32 words per A row
constexpr int PADB2 = 40;                        // 16-bit elems per B row
constexpr int A_BYTES2 = BM * PADA2 * 4;         // 18432
constexpr int B_BYTES2 = BN * PADB2 * 2;         // 20480
constexpr int STAGE_BYTES2 = A_BYTES2 + B_BYTES2; // 38912
constexpr int DYN_SMEM2 = STAGES2 * STAGE_BYTES2; // 155648
constexpr int KCH_BIG2 = (NN / SPLITK) / BK2;    // 125

// ---------------- device scratch -------------------
__device__ float g_scores[NN];
__device__ float g_p[NN];
__device__ __nv_bfloat16 g_scaledT16[(size_t)FF * NN]; // B for GEMM1 (bf16)
__device__ __half g_supportT16[(size_t)FF * NN];       // B for GEMM3 (fp16)
__device__ float g_support4[(size_t)NN * FF];  // A for GEMM2
__device__ float g_weightT[FF * FF];           // B for GEMM2 (tf32-rounded)
__device__ float g_part[(size_t)SPLITK * NN * FF];  // split-K partials

// ---------------- PTX helpers ----------------------
DEVFN uint32_t smem_u32(const void* p) {
    uint32_t a;
    asm("{ .reg .u64 t; cvta.to.shared.u64 t, %1; cvt.u32.u64 %0, t; }" : "=r"(a) : "l"(p));
    return a;
}
DEVFN void cp_async16(uint32_t saddr, const void* gaddr, int srcsize) {
    asm volatile("cp.async.cg.shared.global [%0], [%1], 16, %2;"
                 :: "r"(saddr), "l"(gaddr), "r"(srcsize) : "memory");
}
DEVFN void cp_commit() { asm volatile("cp.async.commit_group;" ::: "memory"); }
template <int N> DEVFN void cp_wait() { asm volatile("cp.async.wait_group %0;" :: "n"(N) : "memory"); }

DEVFN uint32_t f2tf32(float x) {
    uint32_t r; asm("cvt.rna.tf32.f32 %0, %1;" : "=r"(r) : "f"(x)); return r;
}
DEVFN float rnd_tf32(float x) { return __uint_as_float(f2tf32(x)); }

DEVFN void mma_tf32(float* c, const uint32_t* a, const uint32_t* b) {
    asm volatile(
        "mma.sync.aligned.m16n8k8.row.col.f32.tf32.tf32.f32 "
        "{%0,%1,%2,%3}, {%4,%5,%6,%7}, {%8,%9}, {%0,%1,%2,%3};"
        : "+f"(c[0]), "+f"(c[1]), "+f"(c[2]), "+f"(c[3])
        : "r"(a[0]), "r"(a[1]), "r"(a[2]), "r"(a[3]), "r"(b[0]), "r"(b[1]));
}

// ---- 16-bit type policy ----
struct BF16Policy {
    using elem = __nv_bfloat16;
    __device__ __forceinline__ static uint32_t pack(float lo, float hi) {
        __nv_bfloat162 h = __float22bfloat162_rn(make_float2(lo, hi));
        return *reinterpret_cast<uint32_t*>(&h);
    }
    __device__ __forceinline__ static void mma(float* c, const uint32_t* a, const uint32_t* b) {
        asm volatile(
            "mma.sync.aligned.m16n8k16.row.col.f32.bf16.bf16.f32 "
            "{%0,%1,%2,%3}, {%4,%5,%6,%7}, {%8,%9}, {%0,%1,%2,%3};"
            : "+f"(c[0]), "+f"(c[1]), "+f"(c[2]), "+f"(c[3])
            : "r"(a[0]), "r"(a[1]), "r"(a[2]), "r"(a[3]), "r"(b[0]), "r"(b[1]));
    }
};
struct FP16Policy {
    using elem = __half;
    __device__ __forceinline__ static uint32_t pack(float lo, float hi) {
        __half2 h = __float22half2_rn(make_float2(lo, hi));
        return *reinterpret_cast<uint32_t*>(&h);
    }
    __device__ __forceinline__ static void mma(float* c, const uint32_t* a, const uint32_t* b) {
        asm volatile(
            "mma.sync.aligned.m16n8k16.row.col.f32.f16.f16.f32 "
            "{%0,%1,%2,%3}, {%4,%5,%6,%7}, {%8,%9}, {%0,%1,%2,%3};"
            : "+f"(c[0]), "+f"(c[1]), "+f"(c[2]), "+f"(c[3])
            : "r"(a[0]), "r"(a[1]), "r"(a[2]), "r"(a[3]), "r"(b[0]), "r"(b[1]));
    }
};

// ========================================================================
// tf32 GEMM partial (GEMM2): P[r,c] = A[r,:] @ B[c,:]^T
// ========================================================================
__global__ void __launch_bounds__(512, 1)
gemm_tf32(const float* __restrict__ A, int lda,
          const float* __restrict__ B, int ldb,
          int M, int kChunks,
          float* __restrict__ P) {
    extern __shared__ float sm[];

    const int tid  = threadIdx.x;
    const int wid  = tid >> 5;
    const int lane = tid & 31;
    const int l4   = lane >> 2;
    const int lm   = lane & 3;
    const int m0   = blockIdx.x * BM;
    const int wm   = (wid >> 2) * 32;
    const int wn   = (wid & 3) * 64;
    const size_t kStart = (size_t)blockIdx.y * kChunks * BK;
    float* __restrict__ Pp = P + (size_t)blockIdx.y * NN * FF;

    float acc[2][8][4];
#pragma unroll
    for (int mt = 0; mt < 2; ++mt)
#pragma unroll
        for (int nt = 0; nt < 8; ++nt)
#pragma unroll
            for (int e = 0; e < 4; ++e) acc[mt][nt][e] = 0.f;

    auto issue_tile = [&](int c) {
        const int s = c & (STAGES - 1);
        const uint32_t dbase = smem_u32(sm + s * STAGE_WORDS);
        const float* gA = A + (size_t)m0 * lda + kStart + (size_t)c * BK;
        const float* gB = B + kStart + (size_t)c * BK;
#pragma unroll
        for (int t = 0; t < 3; ++t) {
            const int idx = tid + t * 512;
            const float* g;
            uint32_t soff;
            int sz = 16;
            if (idx < 512) {
                const int row = idx >> 2, seg = idx & 3;
                soff = (uint32_t)(row * PAD + seg * 4) * 4;
                g = gA + (size_t)row * lda + seg * 4;
                if (m0 + row >= M) { sz = 0; g = A; }
            } else {
                const int j = idx - 512;
                const int row = j >> 2, seg = j & 3;
                soff = (uint32_t)(A_WORDS + row * PAD + seg * 4) * 4;
                g = gB + (size_t)row * ldb + seg * 4;
            }
            cp_async16(dbase + soff, g, sz);
        }
        cp_commit();
    };

    const int npre = (kChunks < STAGES - 1) ? kChunks : (STAGES - 1);
    for (int c = 0; c < npre; ++c) issue_tile(c);

    for (int c = 0; c < kChunks; ++c) {
        cp_wait<STAGES - 2>();
        __syncthreads();
        if (c + STAGES - 1 < kChunks) issue_tile(c + STAGES - 1);
        else cp_commit();

        const float* sA = sm + (c & (STAGES - 1)) * STAGE_WORDS;
        const float* sB = sA + A_WORDS;

#pragma unroll
        for (int ks = 0; ks < BK; ks += 8) {
            uint32_t af[2][4];
#pragma unroll
            for (int mt = 0; mt < 2; ++mt) {
                const int r = wm + mt * 16 + l4;
                af[mt][0] = f2tf32(sA[r * PAD + ks + lm]);
                af[mt][1] = f2tf32(sA[(r + 8) * PAD + ks + lm]);
                af[mt][2] = f2tf32(sA[r * PAD + ks + lm + 4]);
                af[mt][3] = f2tf32(sA[(r + 8) * PAD + ks + lm + 4]);
            }
            uint32_t bf[8][2];
#pragma unroll
            for (int nt = 0; nt < 8; ++nt) {
                const int n = wn + nt * 8 + l4;
                bf[nt][0] = __float_as_uint(sB[n * PAD + ks + lm]);
                bf[nt][1] = __float_as_uint(sB[n * PAD + ks + lm + 4]);
            }
#pragma unroll
            for (int mt = 0; mt < 2; ++mt)
#pragma unroll
                for (int nt = 0; nt < 8; ++nt)
                    mma_tf32(acc[mt][nt], af[mt], bf[nt]);
        }
    }

#pragma unroll
    for (int mt = 0; mt < 2; ++mt) {
#pragma unroll
        for (int half = 0; half < 2; ++half) {
            const int r = m0 + wm + mt * 16 + l4 + half * 8;
            if (r >= M) continue;
#pragma unroll
            for (int nt = 0; nt < 8; ++nt) {
                const int cb = wn + nt * 8 + lm * 2;
                float2 v = make_float2(acc[mt][nt][half * 2], acc[mt][nt][half * 2 + 1]);
                *reinterpret_cast<float2*>(&Pp[(size_t)r * FF + cb]) = v;
            }
        }
    }
}

// ========================================================================
// 16-bit GEMM partial (GEMM1/GEMM3): P[r,c] = h(A[r,:]) @ B16[c,:]^T
// ========================================================================
template <typename POL>
__global__ void __launch_bounds__(512, 1)
gemm_h16(const float* __restrict__ A, int lda,
         const typename POL::elem* __restrict__ B16, int ldb,
         int M, int kChunks,
         float* __restrict__ P) {
    extern __shared__ char sm2[];

    const int tid  = threadIdx.x;
    const int wid  = tid >> 5;
    const int lane = tid & 31;
    const int l4   = lane >> 2;
    const int lm   = lane & 3;
    const int m0   = blockIdx.x * BM;
    const int wm   = (wid >> 2) * 32;
    const int wn   = (wid & 3) * 64;
    const size_t kStart = (size_t)blockIdx.y * kChunks * BK2;
    float* __restrict__ Pp = P + (size_t)blockIdx.y * NN * FF;

    float acc[2][8][4];
#pragma unroll
    for (int mt = 0; mt < 2; ++mt)
#pragma unroll
        for (int nt = 0; nt < 8; ++nt)
#pragma unroll
            for (int e = 0; e < 4; ++e) acc[mt][nt][e] = 0.f;

    auto issue_tile = [&](int c) {
        const int s = c & (STAGES2 - 1);
        const uint32_t dbase = smem_u32(sm2 + s * STAGE_BYTES2);
        const float* gA = A + (size_t)m0 * lda + kStart + (size_t)c * BK2;
        const typename POL::elem* gB = B16 + kStart + (size_t)c * BK2;
#pragma unroll
        for (int t = 0; t < 4; ++t) {
            const int idx = tid + t * 512;
            const void* g;
            uint32_t soff;
            int sz = 16;
            if (idx < 1024) {                  // A: 128 rows x 8 segs (fp32)
                const int row = idx >> 3, seg = idx & 7;
                soff = (uint32_t)(row * PADA2 + seg * 4) * 4;
                g = gA + (size_t)row * lda + seg * 4;
                if (m0 + row >= M) { sz = 0; g = A; }
            } else {                           // B: 256 rows x 4 segs (16-bit)
                const int j = idx - 1024;
                const int row = j >> 2, seg = j & 3;
                soff = A_BYTES2 + (uint32_t)(row * PADB2 + seg * 8) * 2;
                g = gB + (size_t)row * ldb + seg * 8;
            }
            cp_async16(dbase + soff, g, sz);
        }
        cp_commit();
    };

    const int npre = (kChunks < STAGES2 - 1) ? kChunks : (STAGES2 - 1);
    for (int c = 0; c < npre; ++c) issue_tile(c);

    for (int c = 0; c < kChunks; ++c) {
        cp_wait<STAGES2 - 2>();
        __syncthreads();
        if (c + STAGES2 - 1 < kChunks) issue_tile(c + STAGES2 - 1);
        else cp_commit();

        const char* stage = sm2 + (c & (STAGES2 - 1)) * STAGE_BYTES2;
        const float* sA = reinterpret_cast<const float*>(stage);
        const uint32_t* sB = reinterpret_cast<const uint32_t*>(stage + A_BYTES2);

#pragma unroll
        for (int ks = 0; ks < BK2; ks += 16) {
            uint32_t af[2][4];
#pragma unroll
            for (int mt = 0; mt < 2; ++mt) {
                const int r0 = wm + mt * 16 + l4;
                const float* pr0 = sA + r0 * PADA2 + ks + 2 * lm;
                const float* pr1 = sA + (r0 + 8) * PADA2 + ks + 2 * lm;
                float2 x0 = *reinterpret_cast<const float2*>(pr0);
                float2 x1 = *reinterpret_cast<const float2*>(pr1);
                float2 x2 = *reinterpret_cast<const float2*>(pr0 + 8);
                float2 x3 = *reinterpret_cast<const float2*>(pr1 + 8);
                af[mt][0] = POL::pack(x0.x, x0.y);
                af[mt][1] = POL::pack(x1.x, x1.y);
                af[mt][2] = POL::pack(x2.x, x2.y);
                af[mt][3] = POL::pack(x3.x, x3.y);
            }
            uint32_t bf[8][2];
#pragma unroll
            for (int nt = 0; nt < 8; ++nt) {
                const int n = wn + nt * 8 + l4;
                const int base = (n * PADB2 + ks + 2 * lm) >> 1;
                bf[nt][0] = sB[base];
                bf[nt][1] = sB[base + 4];
            }
#pragma unroll
            for (int mt = 0; mt < 2; ++mt)
#pragma unroll
                for (int nt = 0; nt < 8; ++nt)
                    POL::mma(acc[mt][nt], af[mt], bf[nt]);
        }
    }

#pragma unroll
    for (int mt = 0; mt < 2; ++mt) {
#pragma unroll
        for (int half = 0; half < 2; ++half) {
            const int r = m0 + wm + mt * 16 + l4 + half * 8;
            if (r >= M) continue;
#pragma unroll
            for (int nt = 0; nt < 8; ++nt) {
                const int cb = wn + nt * 8 + lm * 2;
                float2 v = make_float2(acc[mt][nt][half * 2], acc[mt][nt][half * 2 + 1]);
                *reinterpret_cast<float2*>(&Pp[(size_t)r * FF + cb]) = v;
            }
        }
    }
}

// ========================================================================
// reduction / epilogue kernels
// ========================================================================
__global__ void reduce_alpha_kernel(const float* __restrict__ inp,
                                    const float* __restrict__ alphaPtr) {
    const size_t i = ((size_t)blockIdx.x * blockDim.x + threadIdx.x) * 4;
    const float alpha = alphaPtr[0];
    float4 p0 = *reinterpret_cast<const float4*>(&g_part[i]);
    float4 p1 = *reinterpret_cast<const float4*>(&g_part[(size_t)NN * FF + i]);
    float4 p2 = *reinterpret_cast<const float4*>(&g_part[(size_t)2 * NN * FF + i]);
    float4 x  = *reinterpret_cast<const float4*>(&inp[i]);
    float4 r;
    r.x = p0.x + p1.x + p2.x + alpha * x.x;
    r.y = p0.y + p1.y + p2.y + alpha * x.y;
    r.z = p0.z + p1.z + p2.z + alpha * x.z;
    r.w = p0.w + p1.w + p2.w + alpha * x.w;
    *reinterpret_cast<float4*>(&g_support4[i]) = r;
}

__global__ void reduce_sum_kernel(float* __restrict__ out) {
    const size_t i = ((size_t)blockIdx.x * blockDim.x + threadIdx.x) * 4;
    float4 p0 = *reinterpret_cast<const float4*>(&g_part[i]);
    float4 p1 = *reinterpret_cast<const float4*>(&g_part[(size_t)NN * FF + i]);
    float4 p2 = *reinterpret_cast<const float4*>(&g_part[(size_t)2 * NN * FF + i]);
    float4 r;
    r.x = p0.x + p1.x + p2.x;
    r.y = p0.y + p1.y + p2.y;
    r.z = p0.z + p1.z + p2.z;
    r.w = p0.w + p1.w + p2.w;
    *reinterpret_cast<float4*>(&out[i]) = r;
}

// supportT16[c*NN + r] = fp16( part0[r*FF + c] )
__global__ void transT_kernel() {
    __shared__ float t[32][33];
    const int tx = threadIdx.x, ty = threadIdx.y;
    const int r0 = blockIdx.x * 32, c0 = blockIdx.y * 32;
    t[ty][tx] = g_part[(size_t)(r0 + ty) * FF + c0 + tx];
    __syncthreads();
    g_supportT16[(size_t)(c0 + ty) * NN + r0 + tx] = __float2half_rn(t[tx][ty]);
}

// ========================================================================
// prologue kernels
// ========================================================================
__global__ void scores_kernel(const float* __restrict__ input,
                              const float* __restrict__ attn) {
    const int gw   = (blockIdx.x * blockDim.x + threadIdx.x) >> 5;
    const int lane = threadIdx.x & 31;
    if (gw >= NN) return;
    const float* row = input + (size_t)gw * FF;
    float s = 0.f;
#pragma unroll
    for (int j = 0; j < FF / 32; ++j)
        s += row[lane + 32 * j] * __ldg(&attn[lane + 32 * j]);
#pragma unroll
    for (int o = 16; o; o >>= 1) s += __shfl_xor_sync(0xFFFFFFFFu, s, o);
    if (lane == 0) g_scores[gw] = s;
}

__global__ void softmax_kernel() {
    const int tid = threadIdx.x, lane = tid & 31, warp = tid >> 5;
    __shared__ float red[32];
    __shared__ float s_max, s_sum;
    float m = -3.4e38f;
    for (int i = tid; i < NN; i += 1024) m = fmaxf(m, g_scores[i]);
#pragma unroll
    for (int o = 16; o; o >>= 1) m = fmaxf(m, __shfl_xor_sync(0xFFFFFFFFu, m, o));
    if (lane == 0) red[warp] = m;
    __syncthreads();
    if (warp == 0) {
        m = red[lane];
#pragma unroll
        for (int o = 16; o; o >>= 1) m = fmaxf(m, __shfl_xor_sync(0xFFFFFFFFu, m, o));
        if (lane == 0) s_max = m;
    }
    __syncthreads();
    const float mx = s_max;
    float s = 0.f;
    for (int i = tid; i < NN; i += 1024) s += expf(g_scores[i] - mx);
#pragma unroll
    for (int o = 16; o; o >>= 1) s += __shfl_xor_sync(0xFFFFFFFFu, s, o);
    if (lane == 0) red[warp] = s;
    __syncthreads();
    if (warp == 0) {
        s = red[lane];
#pragma unroll
        for (int o = 16; o; o >>= 1) s += __shfl_xor_sync(0xFFFFFFFFu, s, o);
        if (lane == 0) s_sum = s;
    }
    __syncthreads();
    const float inv = 1.0f / s_sum;
    for (int i = tid; i < NN; i += 1024) g_p[i] = expf(g_scores[i] - mx) * inv;
}

// scaledT16[f, i] = bf16( p[i] * input[i, f] )
__global__ void scaledT_kernel(const float* __restrict__ input) {
    __shared__ float t[32][33];
    const int tx = threadIdx.x, ty = threadIdx.y;
    const int i0 = blockIdx.x * 32, f0 = blockIdx.y * 32;
    const int i = i0 + ty, f = f0 + tx;
    t[ty][tx] = g_p[i] * input[(size_t)i * FF + f];
    __syncthreads();
    g_scaledT16[(size_t)(f0 + ty) * NN + i0 + tx] = __float2bfloat16_rn(t[tx][ty]);
}

// weightT[o, i] = tf32( weight[i, o] )
__global__ void weightT_kernel(const float* __restrict__ weight) {
    __shared__ float t[32][33];
    const int tx = threadIdx.x, ty = threadIdx.y;
    const int i0 = blockIdx.x * 32, o0 = blockIdx.y * 32;
    t[ty][tx] = rnd_tf32(weight[(size_t)(i0 + ty) * FF + o0 + tx]);
    __syncthreads();
    g_weightT[(size_t)(o0 + ty) * FF + i0 + tx] = t[tx][ty];
}

// ========================================================================
// launch
// ========================================================================
extern "C" void kernel_launch(void* const* d_in, const int* in_sizes, int n_in,
                              void* d_out, int out_size) {
    const float* input  = (const float*)d_in[0];
    const float* adj    = (const float*)d_in[1];
    const float* inc    = (const float*)d_in[2];
    const float* weight = (const float*)d_in[3];
    const float* attn   = (const float*)d_in[4];
    const float* alpha  = (const float*)d_in[5];
    float* out = (float*)d_out;

    cudaFuncSetAttribute(gemm_tf32,
                         cudaFuncAttributeMaxDynamicSharedMemorySize, DYN_SMEM);
    cudaFuncSetAttribute(gemm_h16<BF16Policy>,
                         cudaFuncAttributeMaxDynamicSharedMemorySize, DYN_SMEM2);
    cudaFuncSetAttribute(gemm_h16<FP16Policy>,
                         cudaFuncAttributeMaxDynamicSharedMemorySize, DYN_SMEM2);

    __nv_bfloat16* scaledT16;
    __half* supportT16;
    float *support4, *weightT, *part;
    cudaGetSymbolAddress((void**)&scaledT16,  g_scaledT16);
    cudaGetSymbolAddress((void**)&supportT16, g_supportT16);
    cudaGetSymbolAddress((void**)&support4,   g_support4);
    cudaGetSymbolAddress((void**)&weightT,    g_weightT);
    cudaGetSymbolAddress((void**)&part,       g_part);

    scores_kernel<<<(NN + 7) / 8, 256>>>(input, attn);
    softmax_kernel<<<1, 1024>>>();
    scaledT_kernel<<<dim3(NN / 32, FF / 32), dim3(32, 32)>>>(input);
    weightT_kernel<<<dim3(FF / 32, FF / 32), dim3(32, 32)>>>(weight);

    const int gridM = (NN + BM - 1) / BM;        // 94
    const int redBlocks = (NN * FF / 4) / 1024;  // 750

    // GEMM1 (bf16): partials of adj @ scaled  (split-K=3)
    gemm_h16<BF16Policy><<<dim3(gridM, SPLITK), 512, DYN_SMEM2>>>(
        adj, NN, scaledT16, NN, NN, KCH_BIG2, part);
    reduce_alpha_kernel<<<redBlocks, 1024>>>(input, alpha);

    // GEMM2 (tf32): part0 = support4 @ weight
    gemm_tf32<<<dim3(gridM, 1), 512, DYN_SMEM>>>(support4, FF, weightT, FF,
                                                 NN, FF / BK, part);
    transT_kernel<<<dim3(NN / 32, FF / 32), dim3(32, 32)>>>();

    // GEMM3 (fp16): partials of incidence @ support  (split-K=3)
    gemm_h16<FP16Policy><<<dim3(gridM, SPLITK), 512, DYN_SMEM2>>>(
        inc, NN, supportT16, NN, NN, KCH_BIG2, part);
    reduce_sum_kernel<<<redBlocks, 1024>>>(out);

    (void)in_sizes; (void)n_in; (void)out_size;
}

// round 7
// speedup vs baseline: 2.4741x; 1.0405x over previous
#include <cuda_runtime.h>
#include <cuda_bf16.h>
#include <cuda_fp16.h>
#include <cstdint>
#include <math.h>

#define DEVFN static __device__ __forceinline__

// ---------------- problem constants ----------------
constexpr int NN = 12000;
constexpr int FF = 256;

// ---------------- GEMM config ----------------
constexpr int BM = 128;
constexpr int BN = 256;
constexpr int SPLITK = 3;

constexpr int BK2 = 32;
constexpr int STAGES2 = 4;
constexpr int PADA2 = 36;                        // fp32 words per A row
constexpr int PADB2 = 40;                        // 16-bit elems per B row (80 B rows)
constexpr int A_BYTES2 = BM * PADA2 * 4;         // 18432
constexpr int B_BYTES2 = BN * PADB2 * 2;         // 20480
constexpr int STAGE_BYTES2 = A_BYTES2 + B_BYTES2; // 38912
constexpr int DYN_SMEM2 = STAGES2 * STAGE_BYTES2; // 155648
constexpr int KCH_BIG2 = (NN / SPLITK) / BK2;    // 125

// ---------------- device scratch -------------------
__device__ float g_scores[NN];
__device__ float g_p[NN];
__device__ __nv_bfloat16 g_scaledT16[(size_t)FF * NN]; // B for GEMM1 (bf16)
__device__ __half g_supportT16[(size_t)FF * NN];       // B for GEMM3 (fp16)
__device__ __half g_weightT16[FF * FF];                // B for GEMM2 (fp16)
__device__ float g_support4[(size_t)NN * FF];  // A for GEMM2
__device__ float g_part[(size_t)SPLITK * NN * FF];  // split-K partials

// ---------------- PTX helpers ----------------------
DEVFN uint32_t smem_u32(const void* p) {
    uint32_t a;
    asm("{ .reg .u64 t; cvta.to.shared.u64 t, %1; cvt.u32.u64 %0, t; }" : "=r"(a) : "l"(p));
    return a;
}
DEVFN void cp_async16(uint32_t saddr, const void* gaddr, int srcsize) {
    asm volatile("cp.async.cg.shared.global [%0], [%1], 16, %2;"
                 :: "r"(saddr), "l"(gaddr), "r"(srcsize) : "memory");
}
DEVFN void cp_commit() { asm volatile("cp.async.commit_group;" ::: "memory"); }
template <int N> DEVFN void cp_wait() { asm volatile("cp.async.wait_group %0;" :: "n"(N) : "memory"); }

DEVFN void ldmatrix_x4(uint32_t& r0, uint32_t& r1, uint32_t& r2, uint32_t& r3,
                       uint32_t addr) {
    asm volatile("ldmatrix.sync.aligned.m8n8.x4.shared.b16 {%0,%1,%2,%3}, [%4];"
                 : "=r"(r0), "=r"(r1), "=r"(r2), "=r"(r3) : "r"(addr));
}

// ---- 16-bit type policy ----
struct BF16Policy {
    using elem = __nv_bfloat16;
    __device__ __forceinline__ static uint32_t pack(float lo, float hi) {
        __nv_bfloat162 h = __float22bfloat162_rn(make_float2(lo, hi));
        return *reinterpret_cast<uint32_t*>(&h);
    }
    __device__ __forceinline__ static void mma(float* c, const uint32_t* a, const uint32_t* b) {
        asm volatile(
            "mma.sync.aligned.m16n8k16.row.col.f32.bf16.bf16.f32 "
            "{%0,%1,%2,%3}, {%4,%5,%6,%7}, {%8,%9}, {%0,%1,%2,%3};"
            : "+f"(c[0]), "+f"(c[1]), "+f"(c[2]), "+f"(c[3])
            : "r"(a[0]), "r"(a[1]), "r"(a[2]), "r"(a[3]), "r"(b[0]), "r"(b[1]));
    }
};
struct FP16Policy {
    using elem = __half;
    __device__ __forceinline__ static uint32_t pack(float lo, float hi) {
        __half2 h = __float22half2_rn(make_float2(lo, hi));
        return *reinterpret_cast<uint32_t*>(&h);
    }
    __device__ __forceinline__ static void mma(float* c, const uint32_t* a, const uint32_t* b) {
        asm volatile(
            "mma.sync.aligned.m16n8k16.row.col.f32.f16.f16.f32 "
            "{%0,%1,%2,%3}, {%4,%5,%6,%7}, {%8,%9}, {%0,%1,%2,%3};"
            : "+f"(c[0]), "+f"(c[1]), "+f"(c[2]), "+f"(c[3])
            : "r"(a[0]), "r"(a[1]), "r"(a[2]), "r"(a[3]), "r"(b[0]), "r"(b[1]));
    }
};

// ========================================================================
// 16-bit GEMM partial: P[r,c] = h(A[r,:]) @ B16[c,:]^T
//   A fp32 in smem, packed per-fragment; B16 via ldmatrix.x4.
// ========================================================================
template <typename POL>
__global__ void __launch_bounds__(512, 1)
gemm_h16(const float* __restrict__ A, int lda,
         const typename POL::elem* __restrict__ B16, int ldb,
         int M, int kChunks,
         float* __restrict__ P) {
    extern __shared__ char sm2[];

    const int tid  = threadIdx.x;
    const int wid  = tid >> 5;
    const int lane = tid & 31;
    const int l4   = lane >> 2;
    const int lm   = lane & 3;
    const int m0   = blockIdx.x * BM;
    const int wm   = (wid >> 2) * 32;   // 0,32,64,96
    const int wn   = (wid & 3) * 64;    // 0,64,128,192
    const size_t kStart = (size_t)blockIdx.y * kChunks * BK2;
    float* __restrict__ Pp = P + (size_t)blockIdx.y * NN * FF;

    // per-lane ldmatrix row-address offset (bytes, within B region):
    // lane octet q supplies rows of matrix q: q>>1 selects nt within pair,
    // q&1 selects k half. Row r = lane&7.
    const int q = lane >> 3;
    const int rr = lane & 7;
    const uint32_t boff_lane =
        (uint32_t)((wn + (q >> 1) * 8 + rr) * PADB2 * 2 + (q & 1) * 16);

    float acc[2][8][4];
#pragma unroll
    for (int mt = 0; mt < 2; ++mt)
#pragma unroll
        for (int nt = 0; nt < 8; ++nt)
#pragma unroll
            for (int e = 0; e < 4; ++e) acc[mt][nt][e] = 0.f;

    auto issue_tile = [&](int c) {
        const int s = c & (STAGES2 - 1);
        const uint32_t dbase = smem_u32(sm2 + s * STAGE_BYTES2);
        const float* gA = A + (size_t)m0 * lda + kStart + (size_t)c * BK2;
        const typename POL::elem* gB = B16 + kStart + (size_t)c * BK2;
#pragma unroll
        for (int t = 0; t < 4; ++t) {
            const int idx = tid + t * 512;
            const void* g;
            uint32_t soff;
            int sz = 16;
            if (idx < 1024) {                  // A: 128 rows x 8 segs (fp32)
                const int row = idx >> 3, seg = idx & 7;
                soff = (uint32_t)(row * PADA2 + seg * 4) * 4;
                g = gA + (size_t)row * lda + seg * 4;
                if (m0 + row >= M) { sz = 0; g = A; }
            } else {                           // B: 256 rows x 4 segs (16-bit)
                const int j = idx - 1024;
                const int row = j >> 2, seg = j & 3;
                soff = A_BYTES2 + (uint32_t)(row * PADB2 + seg * 8) * 2;
                g = gB + (size_t)row * ldb + seg * 8;
            }
            cp_async16(dbase + soff, g, sz);
        }
        cp_commit();
    };

    const int npre = (kChunks < STAGES2 - 1) ? kChunks : (STAGES2 - 1);
    for (int c = 0; c < npre; ++c) issue_tile(c);

    for (int c = 0; c < kChunks; ++c) {
        cp_wait<STAGES2 - 2>();
        __syncthreads();
        if (c + STAGES2 - 1 < kChunks) issue_tile(c + STAGES2 - 1);
        else cp_commit();

        const char* stage = sm2 + (c & (STAGES2 - 1)) * STAGE_BYTES2;
        const float* sA = reinterpret_cast<const float*>(stage);
        const uint32_t bB = smem_u32(stage + A_BYTES2) + boff_lane;

#pragma unroll
        for (int ks = 0; ks < BK2; ks += 16) {
            uint32_t af[2][4];
#pragma unroll
            for (int mt = 0; mt < 2; ++mt) {
                const int r0 = wm + mt * 16 + l4;
                const float* pr0 = sA + r0 * PADA2 + ks + 2 * lm;
                const float* pr1 = sA + (r0 + 8) * PADA2 + ks + 2 * lm;
                float2 x0 = *reinterpret_cast<const float2*>(pr0);
                float2 x1 = *reinterpret_cast<const float2*>(pr1);
                float2 x2 = *reinterpret_cast<const float2*>(pr0 + 8);
                float2 x3 = *reinterpret_cast<const float2*>(pr1 + 8);
                af[mt][0] = POL::pack(x0.x, x0.y);
                af[mt][1] = POL::pack(x1.x, x1.y);
                af[mt][2] = POL::pack(x2.x, x2.y);
                af[mt][3] = POL::pack(x3.x, x3.y);
            }
            uint32_t bf[8][2];
#pragma unroll
            for (int i = 0; i < 4; ++i) {      // each ldmatrix.x4 covers 2 nt tiles
                const uint32_t addr = bB + (uint32_t)(i * 16 * PADB2 * 2 + ks * 2);
                ldmatrix_x4(bf[2 * i][0], bf[2 * i][1],
                            bf[2 * i + 1][0], bf[2 * i + 1][1], addr);
            }
#pragma unroll
            for (int mt = 0; mt < 2; ++mt)
#pragma unroll
                for (int nt = 0; nt < 8; ++nt)
                    POL::mma(acc[mt][nt], af[mt], bf[nt]);
        }
    }

#pragma unroll
    for (int mt = 0; mt < 2; ++mt) {
#pragma unroll
        for (int half = 0; half < 2; ++half) {
            const int r = m0 + wm + mt * 16 + l4 + half * 8;
            if (r >= M) continue;
#pragma unroll
            for (int nt = 0; nt < 8; ++nt) {
                const int cb = wn + nt * 8 + lm * 2;
                float2 v = make_float2(acc[mt][nt][half * 2], acc[mt][nt][half * 2 + 1]);
                *reinterpret_cast<float2*>(&Pp[(size_t)r * FF + cb]) = v;
            }
        }
    }
}

// ========================================================================
// reduction / epilogue kernels
// ========================================================================
__global__ void reduce_alpha_kernel(const float* __restrict__ inp,
                                    const float* __restrict__ alphaPtr) {
    const size_t i = ((size_t)blockIdx.x * blockDim.x + threadIdx.x) * 4;
    const float alpha = alphaPtr[0];
    float4 p0 = *reinterpret_cast<const float4*>(&g_part[i]);
    float4 p1 = *reinterpret_cast<const float4*>(&g_part[(size_t)NN * FF + i]);
    float4 p2 = *reinterpret_cast<const float4*>(&g_part[(size_t)2 * NN * FF + i]);
    float4 x  = *reinterpret_cast<const float4*>(&inp[i]);
    float4 r;
    r.x = p0.x + p1.x + p2.x + alpha * x.x;
    r.y = p0.y + p1.y + p2.y + alpha * x.y;
    r.z = p0.z + p1.z + p2.z + alpha * x.z;
    r.w = p0.w + p1.w + p2.w + alpha * x.w;
    *reinterpret_cast<float4*>(&g_support4[i]) = r;
}

__global__ void reduce_sum_kernel(float* __restrict__ out) {
    const size_t i = ((size_t)blockIdx.x * blockDim.x + threadIdx.x) * 4;
    float4 p0 = *reinterpret_cast<const float4*>(&g_part[i]);
    float4 p1 = *reinterpret_cast<const float4*>(&g_part[(size_t)NN * FF + i]);
    float4 p2 = *reinterpret_cast<const float4*>(&g_part[(size_t)2 * NN * FF + i]);
    float4 r;
    r.x = p0.x + p1.x + p2.x;
    r.y = p0.y + p1.y + p2.y;
    r.z = p0.z + p1.z + p2.z;
    r.w = p0.w + p1.w + p2.w;
    *reinterpret_cast<float4*>(&out[i]) = r;
}

// supportT16[c*NN + r] = fp16( part0[r*FF + c] )
__global__ void transT_kernel() {
    __shared__ float t[32][33];
    const int tx = threadIdx.x, ty = threadIdx.y;
    const int r0 = blockIdx.x * 32, c0 = blockIdx.y * 32;
    t[ty][tx] = g_part[(size_t)(r0 + ty) * FF + c0 + tx];
    __syncthreads();
    g_supportT16[(size_t)(c0 + ty) * NN + r0 + tx] = __float2half_rn(t[tx][ty]);
}

// ========================================================================
// prologue kernels
// ========================================================================
__global__ void scores_kernel(const float* __restrict__ input,
                              const float* __restrict__ attn) {
    const int gw   = (blockIdx.x * blockDim.x + threadIdx.x) >> 5;
    const int lane = threadIdx.x & 31;
    if (gw >= NN) return;
    const float* row = input + (size_t)gw * FF;
    float s = 0.f;
#pragma unroll
    for (int j = 0; j < FF / 32; ++j)
        s += row[lane + 32 * j] * __ldg(&attn[lane + 32 * j]);
#pragma unroll
    for (int o = 16; o; o >>= 1) s += __shfl_xor_sync(0xFFFFFFFFu, s, o);
    if (lane == 0) g_scores[gw] = s;
}

__global__ void softmax_kernel() {
    const int tid = threadIdx.x, lane = tid & 31, warp = tid >> 5;
    __shared__ float red[32];
    __shared__ float s_max, s_sum;
    float m = -3.4e38f;
    for (int i = tid; i < NN; i += 1024) m = fmaxf(m, g_scores[i]);
#pragma unroll
    for (int o = 16; o; o >>= 1) m = fmaxf(m, __shfl_xor_sync(0xFFFFFFFFu, m, o));
    if (lane == 0) red[warp] = m;
    __syncthreads();
    if (warp == 0) {
        m = red[lane];
#pragma unroll
        for (int o = 16; o; o >>= 1) m = fmaxf(m, __shfl_xor_sync(0xFFFFFFFFu, m, o));
        if (lane == 0) s_max = m;
    }
    __syncthreads();
    const float mx = s_max;
    float s = 0.f;
    for (int i = tid; i < NN; i += 1024) s += expf(g_scores[i] - mx);
#pragma unroll
    for (int o = 16; o; o >>= 1) s += __shfl_xor_sync(0xFFFFFFFFu, s, o);
    if (lane == 0) red[warp] = s;
    __syncthreads();
    if (warp == 0) {
        s = red[lane];
#pragma unroll
        for (int o = 16; o; o >>= 1) s += __shfl_xor_sync(0xFFFFFFFFu, s, o);
        if (lane == 0) s_sum = s;
    }
    __syncthreads();
    const float inv = 1.0f / s_sum;
    for (int i = tid; i < NN; i += 1024) g_p[i] = expf(g_scores[i] - mx) * inv;
}

// scaledT16[f, i] = bf16( p[i] * input[i, f] )
__global__ void scaledT_kernel(const float* __restrict__ input) {
    __shared__ float t[32][33];
    const int tx = threadIdx.x, ty = threadIdx.y;
    const int i0 = blockIdx.x * 32, f0 = blockIdx.y * 32;
    const int i = i0 + ty, f = f0 + tx;
    t[ty][tx] = g_p[i] * input[(size_t)i * FF + f];
    __syncthreads();
    g_scaledT16[(size_t)(f0 + ty) * NN + i0 + tx] = __float2bfloat16_rn(t[tx][ty]);
}

// weightT16[o, i] = fp16( weight[i, o] )
__global__ void weightT_kernel(const float* __restrict__ weight) {
    __shared__ float t[32][33];
    const int tx = threadIdx.x, ty = threadIdx.y;
    const int i0 = blockIdx.x * 32, o0 = blockIdx.y * 32;
    t[ty][tx] = weight[(size_t)(i0 + ty) * FF + o0 + tx];
    __syncthreads();
    g_weightT16[(size_t)(o0 + ty) * FF + i0 + tx] = __float2half_rn(t[tx][ty]);
}

// ========================================================================
// launch
// ========================================================================
extern "C" void kernel_launch(void* const* d_in, const int* in_sizes, int n_in,
                              void* d_out, int out_size) {
    const float* input  = (const float*)d_in[0];
    const float* adj    = (const float*)d_in[1];
    const float* inc    = (const float*)d_in[2];
    const float* weight = (const float*)d_in[3];
    const float* attn   = (const float*)d_in[4];
    const float* alpha  = (const float*)d_in[5];
    float* out = (float*)d_out;

    cudaFuncSetAttribute(gemm_h16<BF16Policy>,
                         cudaFuncAttributeMaxDynamicSharedMemorySize, DYN_SMEM2);
    cudaFuncSetAttribute(gemm_h16<FP16Policy>,
                         cudaFuncAttributeMaxDynamicSharedMemorySize, DYN_SMEM2);

    __nv_bfloat16* scaledT16;
    __half *supportT16, *weightT16;
    float *support4, *part;
    cudaGetSymbolAddress((void**)&scaledT16,  g_scaledT16);
    cudaGetSymbolAddress((void**)&supportT16, g_supportT16);
    cudaGetSymbolAddress((void**)&weightT16,  g_weightT16);
    cudaGetSymbolAddress((void**)&support4,   g_support4);
    cudaGetSymbolAddress((void**)&part,       g_part);

    scores_kernel<<<(NN + 7) / 8, 256>>>(input, attn);
    softmax_kernel<<<1, 1024>>>();
    scaledT_kernel<<<dim3(NN / 32, FF / 32), dim3(32, 32)>>>(input);
    weightT_kernel<<<dim3(FF / 32, FF / 32), dim3(32, 32)>>>(weight);

    const int gridM = (NN + BM - 1) / BM;        // 94
    const int redBlocks = (NN * FF / 4) / 1024;  // 750

    // GEMM1 (bf16): partials of adj @ scaled  (split-K=3)
    gemm_h16<BF16Policy><<<dim3(gridM, SPLITK), 512, DYN_SMEM2>>>(
        adj, NN, scaledT16, NN, NN, KCH_BIG2, part);
    reduce_alpha_kernel<<<redBlocks, 1024>>>(input, alpha);

    // GEMM2 (fp16): part0 = support4 @ weight  (K=256)
    gemm_h16<FP16Policy><<<dim3(gridM, 1), 512, DYN_SMEM2>>>(
        support4, FF, weightT16, FF, NN, FF / BK2, part);
    transT_kernel<<<dim3(NN / 32, FF / 32), dim3(32, 32)>>>();

    // GEMM3 (fp16): partials of incidence @ support  (split-K=3)
    gemm_h16<FP16Policy><<<dim3(gridM, SPLITK), 512, DYN_SMEM2>>>(
        inc, NN, supportT16, NN, NN, KCH_BIG2, part);
    reduce_sum_kernel<<<redBlocks, 1024>>>(out);

    (void)in_sizes; (void)n_in; (void)out_size;
}

// round 8
// speedup vs baseline: 3.3227x; 1.3430x over previous
#include <cuda_runtime.h>
#include <cuda_bf16.h>
#include <cuda_fp16.h>
#include <cstdint>
#include <math.h>

#define DEVFN static __device__ __forceinline__

// ---------------- problem constants ----------------
constexpr int NN = 12000;
constexpr int FF = 256;

// ---------------- GEMM config ----------------
constexpr int BM = 128;
constexpr int BN = 256;
constexpr int SPLITK = 3;

constexpr int BK2 = 32;
constexpr int STAGES2 = 4;
constexpr int PADA2 = 40;                         // 16-bit elems per A row (80 B)
constexpr int PADB2 = 40;                         // 16-bit elems per B row (80 B)
constexpr int A_BYTES2 = BM * PADA2 * 2;          // 10240
constexpr int B_BYTES2 = BN * PADB2 * 2;          // 20480
constexpr int STAGE_BYTES2 = A_BYTES2 + B_BYTES2; // 30720
constexpr int DYN_SMEM2 = STAGES2 * STAGE_BYTES2; // 122880
constexpr int KCH_BIG2 = (NN / SPLITK) / BK2;     // 125

// ---------------- device scratch -------------------
__device__ float g_scores[NN];
__device__ float g_p[NN];
__device__ __nv_bfloat16 g_scaledT16[(size_t)FF * NN]; // B for GEMM1 (bf16)
__device__ __half g_supportT16[(size_t)FF * NN];       // B for GEMM3 (fp16)
__device__ __half g_weightT16[FF * FF];                // B for GEMM2 (fp16)
__device__ float g_support4[(size_t)NN * FF];  // A for GEMM2
__device__ float g_part[(size_t)SPLITK * NN * FF];  // split-K partials

// ---------------- PTX helpers ----------------------
DEVFN uint32_t smem_u32(const void* p) {
    uint32_t a;
    asm("{ .reg .u64 t; cvta.to.shared.u64 t, %1; cvt.u32.u64 %0, t; }" : "=r"(a) : "l"(p));
    return a;
}
DEVFN void cp_async16(uint32_t saddr, const void* gaddr, int srcsize) {
    asm volatile("cp.async.cg.shared.global [%0], [%1], 16, %2;"
                 :: "r"(saddr), "l"(gaddr), "r"(srcsize) : "memory");
}
DEVFN void cp_commit() { asm volatile("cp.async.commit_group;" ::: "memory"); }
template <int N> DEVFN void cp_wait() { asm volatile("cp.async.wait_group %0;" :: "n"(N) : "memory"); }

DEVFN void ldmatrix_x4(uint32_t& r0, uint32_t& r1, uint32_t& r2, uint32_t& r3,
                       uint32_t addr) {
    asm volatile("ldmatrix.sync.aligned.m8n8.x4.shared.b16 {%0,%1,%2,%3}, [%4];"
                 : "=r"(r0), "=r"(r1), "=r"(r2), "=r"(r3) : "r"(addr));
}

// ---- 16-bit type policy ----
struct BF16Policy {
    using elem = __nv_bfloat16;
    __device__ __forceinline__ static uint32_t pack(float lo, float hi) {
        __nv_bfloat162 h = __float22bfloat162_rn(make_float2(lo, hi));
        return *reinterpret_cast<uint32_t*>(&h);
    }
    __device__ __forceinline__ static void mma(float* c, const uint32_t* a, const uint32_t* b) {
        asm volatile(
            "mma.sync.aligned.m16n8k16.row.col.f32.bf16.bf16.f32 "
            "{%0,%1,%2,%3}, {%4,%5,%6,%7}, {%8,%9}, {%0,%1,%2,%3};"
            : "+f"(c[0]), "+f"(c[1]), "+f"(c[2]), "+f"(c[3])
            : "r"(a[0]), "r"(a[1]), "r"(a[2]), "r"(a[3]), "r"(b[0]), "r"(b[1]));
    }
};
struct FP16Policy {
    using elem = __half;
    __device__ __forceinline__ static uint32_t pack(float lo, float hi) {
        __half2 h = __float22half2_rn(make_float2(lo, hi));
        return *reinterpret_cast<uint32_t*>(&h);
    }
    __device__ __forceinline__ static void mma(float* c, const uint32_t* a, const uint32_t* b) {
        asm volatile(
            "mma.sync.aligned.m16n8k16.row.col.f32.f16.f16.f32 "
            "{%0,%1,%2,%3}, {%4,%5,%6,%7}, {%8,%9}, {%0,%1,%2,%3};"
            : "+f"(c[0]), "+f"(c[1]), "+f"(c[2]), "+f"(c[3])
            : "r"(a[0]), "r"(a[1]), "r"(a[2]), "r"(a[3]), "r"(b[0]), "r"(b[1]));
    }
};

// ========================================================================
// 16-bit GEMM partial: P[r,c] = h(A[r,:]) @ B16[c,:]^T
//   A fp32 in gmem -> 16-bit in smem (loader converts, reg-staged pipeline);
//   both operands consumed via ldmatrix.x4.
// ========================================================================
template <typename POL>
__global__ void __launch_bounds__(512, 1)
gemm_h16(const float* __restrict__ A, int lda,
         const typename POL::elem* __restrict__ B16, int ldb,
         int M, int kChunks,
         float* __restrict__ P) {
    extern __shared__ char sm2[];

    const int tid  = threadIdx.x;
    const int wid  = tid >> 5;
    const int lane = tid & 31;
    const int l4   = lane >> 2;
    const int lm   = lane & 3;
    const int m0   = blockIdx.x * BM;
    const int wm   = (wid >> 2) * 32;   // 0,32,64,96
    const int wn   = (wid & 3) * 64;    // 0,64,128,192
    const size_t kStart = (size_t)blockIdx.y * kChunks * BK2;
    float* __restrict__ Pp = P + (size_t)blockIdx.y * NN * FF;

    // B ldmatrix per-lane offset (bytes within B region)
    const int q = lane >> 3;
    const int rr = lane & 7;
    const uint32_t boff_lane =
        (uint32_t)((wn + (q >> 1) * 8 + rr) * PADB2 * 2 + (q & 1) * 16);
    // A ldmatrix per-lane offset (bytes within A region)
    const uint32_t aoff_lane =
        (uint32_t)((wm + (lane & 15)) * PADA2 * 2 + (lane >> 4) * 16);

    // A loader geometry: 128 rows x 4 segs of 8 fp32
    const int arow = tid >> 2;
    const int aseg = tid & 3;
    const bool arow_ok = (m0 + arow) < M;
    const float* gArow = A + (size_t)(m0 + arow) * lda + kStart + aseg * 8;

    float acc[2][8][4];
#pragma unroll
    for (int mt = 0; mt < 2; ++mt)
#pragma unroll
        for (int nt = 0; nt < 8; ++nt)
#pragma unroll
            for (int e = 0; e < 4; ++e) acc[mt][nt][e] = 0.f;

    float4 ra0, ra1;   // staged A data for the upcoming chunk

    auto lda_fetch = [&](int c) {
        if (arow_ok) {
            const float4* g = reinterpret_cast<const float4*>(gArow + (size_t)c * BK2);
            ra0 = __ldg(g);
            ra1 = __ldg(g + 1);
        } else {
            ra0 = make_float4(0.f, 0.f, 0.f, 0.f);
            ra1 = make_float4(0.f, 0.f, 0.f, 0.f);
        }
    };
    auto sts_a = [&](int c) {
        uint4 u;
        u.x = POL::pack(ra0.x, ra0.y);
        u.y = POL::pack(ra0.z, ra0.w);
        u.z = POL::pack(ra1.x, ra1.y);
        u.w = POL::pack(ra1.z, ra1.w);
        char* dst = sm2 + (c & (STAGES2 - 1)) * STAGE_BYTES2
                  + (size_t)arow * (PADA2 * 2) + aseg * 16;
        *reinterpret_cast<uint4*>(dst) = u;
    };
    auto issue_b = [&](int c) {
        const int s = c & (STAGES2 - 1);
        const uint32_t dbase = smem_u32(sm2 + s * STAGE_BYTES2) + A_BYTES2;
        const typename POL::elem* gB = B16 + kStart + (size_t)c * BK2;
#pragma unroll
        for (int t = 0; t < 2; ++t) {
            const int idx = tid + t * 512;          // 1024 segs: 256 rows x 4
            const int row = idx >> 2, seg = idx & 3;
            const uint32_t soff = (uint32_t)(row * PADB2 + seg * 8) * 2;
            cp_async16(dbase + soff, gB + (size_t)row * ldb + seg * 8, 16);
        }
        cp_commit();
    };

    lda_fetch(0);
    const int npre = (kChunks < STAGES2 - 1) ? kChunks : (STAGES2 - 1);
    for (int c = 0; c < npre; ++c) issue_b(c);

    for (int c = 0; c < kChunks; ++c) {
        sts_a(c);
        cp_wait<STAGES2 - 2>();
        __syncthreads();
        if (c + 1 < kChunks) lda_fetch(c + 1);
        if (c + STAGES2 - 1 < kChunks) issue_b(c + STAGES2 - 1);
        else cp_commit();   // keep group counts aligned

        const char* stage = sm2 + (c & (STAGES2 - 1)) * STAGE_BYTES2;
        const uint32_t bA = smem_u32(stage) + aoff_lane;
        const uint32_t bB = smem_u32(stage + A_BYTES2) + boff_lane;

#pragma unroll
        for (int ks = 0; ks < BK2; ks += 16) {
            uint32_t af[2][4];
#pragma unroll
            for (int mt = 0; mt < 2; ++mt)
                ldmatrix_x4(af[mt][0], af[mt][1], af[mt][2], af[mt][3],
                            bA + (uint32_t)(mt * 16 * PADA2 * 2 + ks * 2));
            uint32_t bf[8][2];
#pragma unroll
            for (int i = 0; i < 4; ++i) {
                const uint32_t addr = bB + (uint32_t)(i * 16 * PADB2 * 2 + ks * 2);
                ldmatrix_x4(bf[2 * i][0], bf[2 * i][1],
                            bf[2 * i + 1][0], bf[2 * i + 1][1], addr);
            }
#pragma unroll
            for (int mt = 0; mt < 2; ++mt)
#pragma unroll
                for (int nt = 0; nt < 8; ++nt)
                    POL::mma(acc[mt][nt], af[mt], bf[nt]);
        }
    }

#pragma unroll
    for (int mt = 0; mt < 2; ++mt) {
#pragma unroll
        for (int half = 0; half < 2; ++half) {
            const int r = m0 + wm + mt * 16 + l4 + half * 8;
            if (r >= M) continue;
#pragma unroll
            for (int nt = 0; nt < 8; ++nt) {
                const int cb = wn + nt * 8 + lm * 2;
                float2 v = make_float2(acc[mt][nt][half * 2], acc[mt][nt][half * 2 + 1]);
                *reinterpret_cast<float2*>(&Pp[(size_t)r * FF + cb]) = v;
            }
        }
    }
}

// ========================================================================
// reduction / epilogue kernels
// ========================================================================
__global__ void reduce_alpha_kernel(const float* __restrict__ inp,
                                    const float* __restrict__ alphaPtr) {
    const size_t i = ((size_t)blockIdx.x * blockDim.x + threadIdx.x) * 4;
    const float alpha = alphaPtr[0];
    float4 p0 = *reinterpret_cast<const float4*>(&g_part[i]);
    float4 p1 = *reinterpret_cast<const float4*>(&g_part[(size_t)NN * FF + i]);
    float4 p2 = *reinterpret_cast<const float4*>(&g_part[(size_t)2 * NN * FF + i]);
    float4 x  = *reinterpret_cast<const float4*>(&inp[i]);
    float4 r;
    r.x = p0.x + p1.x + p2.x + alpha * x.x;
    r.y = p0.y + p1.y + p2.y + alpha * x.y;
    r.z = p0.z + p1.z + p2.z + alpha * x.z;
    r.w = p0.w + p1.w + p2.w + alpha * x.w;
    *reinterpret_cast<float4*>(&g_support4[i]) = r;
}

__global__ void reduce_sum_kernel(float* __restrict__ out) {
    const size_t i = ((size_t)blockIdx.x * blockDim.x + threadIdx.x) * 4;
    float4 p0 = *reinterpret_cast<const float4*>(&g_part[i]);
    float4 p1 = *reinterpret_cast<const float4*>(&g_part[(size_t)NN * FF + i]);
    float4 p2 = *reinterpret_cast<const float4*>(&g_part[(size_t)2 * NN * FF + i]);
    float4 r;
    r.x = p0.x + p1.x + p2.x;
    r.y = p0.y + p1.y + p2.y;
    r.z = p0.z + p1.z + p2.z;
    r.w = p0.w + p1.w + p2.w;
    *reinterpret_cast<float4*>(&out[i]) = r;
}

// supportT16[c*NN + r] = fp16( part0[r*FF + c] )
__global__ void transT_kernel() {
    __shared__ float t[32][33];
    const int tx = threadIdx.x, ty = threadIdx.y;
    const int r0 = blockIdx.x * 32, c0 = blockIdx.y * 32;
    t[ty][tx] = g_part[(size_t)(r0 + ty) * FF + c0 + tx];
    __syncthreads();
    g_supportT16[(size_t)(c0 + ty) * NN + r0 + tx] = __float2half_rn(t[tx][ty]);
}

// ========================================================================
// prologue kernels
// ========================================================================
__global__ void scores_kernel(const float* __restrict__ input,
                              const float* __restrict__ attn) {
    const int gw   = (blockIdx.x * blockDim.x + threadIdx.x) >> 5;
    const int lane = threadIdx.x & 31;
    if (gw >= NN) return;
    const float* row = input + (size_t)gw * FF;
    float s = 0.f;
#pragma unroll
    for (int j = 0; j < FF / 32; ++j)
        s += row[lane + 32 * j] * __ldg(&attn[lane + 32 * j]);
#pragma unroll
    for (int o = 16; o; o >>= 1) s += __shfl_xor_sync(0xFFFFFFFFu, s, o);
    if (lane == 0) g_scores[gw] = s;
}

__global__ void softmax_kernel() {
    const int tid = threadIdx.x, lane = tid & 31, warp = tid >> 5;
    __shared__ float red[32];
    __shared__ float s_max, s_sum;
    float m = -3.4e38f;
    for (int i = tid; i < NN; i += 1024) m = fmaxf(m, g_scores[i]);
#pragma unroll
    for (int o = 16; o; o >>= 1) m = fmaxf(m, __shfl_xor_sync(0xFFFFFFFFu, m, o));
    if (lane == 0) red[warp] = m;
    __syncthreads();
    if (warp == 0) {
        m = red[lane];
#pragma unroll
        for (int o = 16; o; o >>= 1) m = fmaxf(m, __shfl_xor_sync(0xFFFFFFFFu, m, o));
        if (lane == 0) s_max = m;
    }
    __syncthreads();
    const float mx = s_max;
    float s = 0.f;
    for (int i = tid; i < NN; i += 1024) s += expf(g_scores[i] - mx);
#pragma unroll
    for (int o = 16; o; o >>= 1) s += __shfl_xor_sync(0xFFFFFFFFu, s, o);
    if (lane == 0) red[warp] = s;
    __syncthreads();
    if (warp == 0) {
        s = red[lane];
#pragma unroll
        for (int o = 16; o; o >>= 1) s += __shfl_xor_sync(0xFFFFFFFFu, s, o);
        if (lane == 0) s_sum = s;
    }
    __syncthreads();
    const float inv = 1.0f / s_sum;
    for (int i = tid; i < NN; i += 1024) g_p[i] = expf(g_scores[i] - mx) * inv;
}

// scaledT16[f, i] = bf16( p[i] * input[i, f] )
__global__ void scaledT_kernel(const float* __restrict__ input) {
    __shared__ float t[32][33];
    const int tx = threadIdx.x, ty = threadIdx.y;
    const int i0 = blockIdx.x * 32, f0 = blockIdx.y * 32;
    const int i = i0 + ty, f = f0 + tx;
    t[ty][tx] = g_p[i] * input[(size_t)i * FF + f];
    __syncthreads();
    g_scaledT16[(size_t)(f0 + ty) * NN + i0 + tx] = __float2bfloat16_rn(t[tx][ty]);
}

// weightT16[o, i] = fp16( weight[i, o] )
__global__ void weightT_kernel(const float* __restrict__ weight) {
    __shared__ float t[32][33];
    const int tx = threadIdx.x, ty = threadIdx.y;
    const int i0 = blockIdx.x * 32, o0 = blockIdx.y * 32;
    t[ty][tx] = weight[(size_t)(i0 + ty) * FF + o0 + tx];
    __syncthreads();
    g_weightT16[(size_t)(o0 + ty) * FF + i0 + tx] = __float2half_rn(t[tx][ty]);
}

// ========================================================================
// launch
// ========================================================================
extern "C" void kernel_launch(void* const* d_in, const int* in_sizes, int n_in,
                              void* d_out, int out_size) {
    const float* input  = (const float*)d_in[0];
    const float* adj    = (const float*)d_in[1];
    const float* inc    = (const float*)d_in[2];
    const float* weight = (const float*)d_in[3];
    const float* attn   = (const float*)d_in[4];
    const float* alpha  = (const float*)d_in[5];
    float* out = (float*)d_out;

    cudaFuncSetAttribute(gemm_h16<BF16Policy>,
                         cudaFuncAttributeMaxDynamicSharedMemorySize, DYN_SMEM2);
    cudaFuncSetAttribute(gemm_h16<FP16Policy>,
                         cudaFuncAttributeMaxDynamicSharedMemorySize, DYN_SMEM2);

    __nv_bfloat16* scaledT16;
    __half *supportT16, *weightT16;
    float *support4, *part;
    cudaGetSymbolAddress((void**)&scaledT16,  g_scaledT16);
    cudaGetSymbolAddress((void**)&supportT16, g_supportT16);
    cudaGetSymbolAddress((void**)&weightT16,  g_weightT16);
    cudaGetSymbolAddress((void**)&support4,   g_support4);
    cudaGetSymbolAddress((void**)&part,       g_part);

    scores_kernel<<<(NN + 7) / 8, 256>>>(input, attn);
    softmax_kernel<<<1, 1024>>>();
    scaledT_kernel<<<dim3(NN / 32, FF / 32), dim3(32, 32)>>>(input);
    weightT_kernel<<<dim3(FF / 32, FF / 32), dim3(32, 32)>>>(weight);

    const int gridM = (NN + BM - 1) / BM;        // 94
    const int redBlocks = (NN * FF / 4) / 1024;  // 750

    // GEMM1 (bf16): partials of adj @ scaled  (split-K=3)
    gemm_h16<BF16Policy><<<dim3(gridM, SPLITK), 512, DYN_SMEM2>>>(
        adj, NN, scaledT16, NN, NN, KCH_BIG2, part);
    reduce_alpha_kernel<<<redBlocks, 1024>>>(input, alpha);

    // GEMM2 (fp16): part0 = support4 @ weight  (K=256)
    gemm_h16<FP16Policy><<<dim3(gridM, 1), 512, DYN_SMEM2>>>(
        support4, FF, weightT16, FF, NN, FF / BK2, part);
    transT_kernel<<<dim3(NN / 32, FF / 32), dim3(32, 32)>>>();

    // GEMM3 (fp16): partials of incidence @ support  (split-K=3)
    gemm_h16<FP16Policy><<<dim3(gridM, SPLITK), 512, DYN_SMEM2>>>(
        inc, NN, supportT16, NN, NN, KCH_BIG2, part);
    reduce_sum_kernel<<<redBlocks, 1024>>>(out);

    (void)in_sizes; (void)n_in; (void)out_size;
}

// round 9
// speedup vs baseline: 3.3699x; 1.0142x over previous
#include <cuda_runtime.h>
#include <cuda_fp16.h>
#include <cstdint>
#include <math.h>

#define DEVFN static __device__ __forceinline__

// ---------------- problem constants ----------------
constexpr int NN = 12000;
constexpr int FF = 256;
constexpr float SCALE1   = 16384.f;      // pre-scale on `scaled` (GEMM1 B)
constexpr float INV_SCALE1 = 1.f / 16384.f;

// ---------------- GEMM config ----------------
constexpr int BM = 128;
constexpr int BN = 256;
constexpr int SPLITK = 3;

constexpr int BK2 = 32;
constexpr int STAGES2 = 4;
constexpr int PADA2 = 40;                         // 16-bit elems per A row (80 B)
constexpr int PADB2 = 40;                         // 16-bit elems per B row (80 B)
constexpr int A_BYTES2 = BM * PADA2 * 2;          // 10240
constexpr int B_BYTES2 = BN * PADB2 * 2;          // 20480
constexpr int STAGE_BYTES2 = A_BYTES2 + B_BYTES2; // 30720
constexpr int DYN_SMEM2 = STAGES2 * STAGE_BYTES2; // 122880
constexpr int KCH_BIG2 = (NN / SPLITK) / BK2;     // 125

// ---------------- device scratch -------------------
__device__ float g_scores[NN];
__device__ float g_p[NN];
__device__ __half g_scaledT16[(size_t)FF * NN];   // B for GEMM1 (fp16, x2^14)
__device__ __half g_supportT16[(size_t)FF * NN];  // B for GEMM3 (fp16)
__device__ __half g_weightT16[FF * FF];           // B for GEMM2 (fp16)
__device__ float g_part[(size_t)SPLITK * NN * FF];  // split-K partials

// ---------------- PTX helpers ----------------------
DEVFN uint32_t smem_u32(const void* p) {
    uint32_t a;
    asm("{ .reg .u64 t; cvta.to.shared.u64 t, %1; cvt.u32.u64 %0, t; }" : "=r"(a) : "l"(p));
    return a;
}
DEVFN void cp_async16(uint32_t saddr, const void* gaddr) {
    asm volatile("cp.async.cg.shared.global [%0], [%1], 16;"
                 :: "r"(saddr), "l"(gaddr) : "memory");
}
DEVFN void cp_commit() { asm volatile("cp.async.commit_group;" ::: "memory"); }
template <int N> DEVFN void cp_wait() { asm volatile("cp.async.wait_group %0;" :: "n"(N) : "memory"); }

DEVFN void ldmatrix_x4(uint32_t& r0, uint32_t& r1, uint32_t& r2, uint32_t& r3,
                       uint32_t addr) {
    asm volatile("ldmatrix.sync.aligned.m8n8.x4.shared.b16 {%0,%1,%2,%3}, [%4];"
                 : "=r"(r0), "=r"(r1), "=r"(r2), "=r"(r3) : "r"(addr));
}
DEVFN uint32_t pack_h2(float lo, float hi) {
    __half2 h = __float22half2_rn(make_float2(lo, hi));
    return *reinterpret_cast<uint32_t*>(&h);
}
DEVFN void mma_fp16(float* c, const uint32_t* a, const uint32_t* b) {
    asm volatile(
        "mma.sync.aligned.m16n8k16.row.col.f32.f16.f16.f32 "
        "{%0,%1,%2,%3}, {%4,%5,%6,%7}, {%8,%9}, {%0,%1,%2,%3};"
        : "+f"(c[0]), "+f"(c[1]), "+f"(c[2]), "+f"(c[3])
        : "r"(a[0]), "r"(a[1]), "r"(a[2]), "r"(a[3]), "r"(b[0]), "r"(b[1]));
}

// ======== shared mainloop pieces (macro-free, duplicated in 2 kernels) ====

// ========================================================================
// GEMM partial (GEMM1/GEMM3): P[r,c] = fp16(A[r,:]) @ B16[c,:]^T
// ========================================================================
__global__ void __launch_bounds__(512, 1)
gemm_h16(const float* __restrict__ A, int lda,
         const __half* __restrict__ B16, int ldb,
         int M, int kChunks,
         float* __restrict__ P) {
    extern __shared__ char sm2[];

    const int tid  = threadIdx.x;
    const int wid  = tid >> 5;
    const int lane = tid & 31;
    const int l4   = lane >> 2;
    const int lm   = lane & 3;
    const int m0   = blockIdx.x * BM;
    const int wm   = (wid >> 2) * 32;
    const int wn   = (wid & 3) * 64;
    const size_t kStart = (size_t)blockIdx.y * kChunks * BK2;
    float* __restrict__ Pp = P + (size_t)blockIdx.y * NN * FF;

    const int q = lane >> 3;
    const int rr = lane & 7;
    const uint32_t boff_lane =
        (uint32_t)((wn + (q >> 1) * 8 + rr) * PADB2 * 2 + (q & 1) * 16);
    const uint32_t aoff_lane =
        (uint32_t)((wm + (lane & 15)) * PADA2 * 2 + (lane >> 4) * 16);

    const int arow = tid >> 2;
    const int aseg = tid & 3;
    const bool arow_ok = (m0 + arow) < M;
    const float* gArow = A + (size_t)(m0 + arow) * lda + kStart + aseg * 8;

    float acc[2][8][4];
#pragma unroll
    for (int mt = 0; mt < 2; ++mt)
#pragma unroll
        for (int nt = 0; nt < 8; ++nt)
#pragma unroll
            for (int e = 0; e < 4; ++e) acc[mt][nt][e] = 0.f;

    float4 ra0, ra1;
    auto lda_fetch = [&](int c) {
        if (arow_ok) {
            const float4* g = reinterpret_cast<const float4*>(gArow + (size_t)c * BK2);
            ra0 = __ldg(g);
            ra1 = __ldg(g + 1);
        } else {
            ra0 = make_float4(0.f, 0.f, 0.f, 0.f);
            ra1 = make_float4(0.f, 0.f, 0.f, 0.f);
        }
    };
    auto sts_a = [&](int c) {
        uint4 u;
        u.x = pack_h2(ra0.x, ra0.y);
        u.y = pack_h2(ra0.z, ra0.w);
        u.z = pack_h2(ra1.x, ra1.y);
        u.w = pack_h2(ra1.z, ra1.w);
        char* dst = sm2 + (c & (STAGES2 - 1)) * STAGE_BYTES2
                  + (size_t)arow * (PADA2 * 2) + aseg * 16;
        *reinterpret_cast<uint4*>(dst) = u;
    };
    auto issue_b = [&](int c) {
        const int s = c & (STAGES2 - 1);
        const uint32_t dbase = smem_u32(sm2 + s * STAGE_BYTES2) + A_BYTES2;
        const __half* gB = B16 + kStart + (size_t)c * BK2;
#pragma unroll
        for (int t = 0; t < 2; ++t) {
            const int idx = tid + t * 512;
            const int row = idx >> 2, seg = idx & 3;
            const uint32_t soff = (uint32_t)(row * PADB2 + seg * 8) * 2;
            cp_async16(dbase + soff, gB + (size_t)row * ldb + seg * 8);
        }
        cp_commit();
    };

    lda_fetch(0);
    const int npre = (kChunks < STAGES2 - 1) ? kChunks : (STAGES2 - 1);
    for (int c = 0; c < npre; ++c) issue_b(c);

    for (int c = 0; c < kChunks; ++c) {
        sts_a(c);
        cp_wait<STAGES2 - 2>();
        __syncthreads();
        if (c + 1 < kChunks) lda_fetch(c + 1);
        if (c + STAGES2 - 1 < kChunks) issue_b(c + STAGES2 - 1);
        else cp_commit();

        const char* stage = sm2 + (c & (STAGES2 - 1)) * STAGE_BYTES2;
        const uint32_t bA = smem_u32(stage) + aoff_lane;
        const uint32_t bB = smem_u32(stage + A_BYTES2) + boff_lane;

#pragma unroll
        for (int ks = 0; ks < BK2; ks += 16) {
            uint32_t af[2][4];
#pragma unroll
            for (int mt = 0; mt < 2; ++mt)
                ldmatrix_x4(af[mt][0], af[mt][1], af[mt][2], af[mt][3],
                            bA + (uint32_t)(mt * 16 * PADA2 * 2 + ks * 2));
            uint32_t bf[8][2];
#pragma unroll
            for (int i = 0; i < 4; ++i) {
                const uint32_t addr = bB + (uint32_t)(i * 16 * PADB2 * 2 + ks * 2);
                ldmatrix_x4(bf[2 * i][0], bf[2 * i][1],
                            bf[2 * i + 1][0], bf[2 * i + 1][1], addr);
            }
#pragma unroll
            for (int mt = 0; mt < 2; ++mt)
#pragma unroll
                for (int nt = 0; nt < 8; ++nt)
                    mma_fp16(acc[mt][nt], af[mt], bf[nt]);
        }
    }

#pragma unroll
    for (int mt = 0; mt < 2; ++mt) {
#pragma unroll
        for (int half = 0; half < 2; ++half) {
            const int r = m0 + wm + mt * 16 + l4 + half * 8;
            if (r >= M) continue;
#pragma unroll
            for (int nt = 0; nt < 8; ++nt) {
                const int cb = wn + nt * 8 + lm * 2;
                float2 v = make_float2(acc[mt][nt][half * 2], acc[mt][nt][half * 2 + 1]);
                *reinterpret_cast<float2*>(&Pp[(size_t)r * FF + cb]) = v;
            }
        }
    }
}

// ========================================================================
// GEMM2 fused: A = sum(partials)*2^-14 + alpha*input (computed in loader),
//              B = weightT16; epilogue writes supportT16 transposed fp16.
// ========================================================================
__global__ void __launch_bounds__(512, 1)
gemm2_fused(const float* __restrict__ inp,
            const float* __restrict__ alphaPtr,
            const __half* __restrict__ B16,
            int M) {
    extern __shared__ char sm2[];
    constexpr int kChunks = FF / BK2;   // 8
    constexpr int ldb = FF;

    const int tid  = threadIdx.x;
    const int wid  = tid >> 5;
    const int lane = tid & 31;
    const int l4   = lane >> 2;
    const int lm   = lane & 3;
    const int m0   = blockIdx.x * BM;
    const int wm   = (wid >> 2) * 32;
    const int wn   = (wid & 3) * 64;
    const float alpha = __ldg(alphaPtr);

    const int q = lane >> 3;
    const int rr = lane & 7;
    const uint32_t boff_lane =
        (uint32_t)((wn + (q >> 1) * 8 + rr) * PADB2 * 2 + (q & 1) * 16);
    const uint32_t aoff_lane =
        (uint32_t)((wm + (lane & 15)) * PADA2 * 2 + (lane >> 4) * 16);

    const int arow = tid >> 2;
    const int aseg = tid & 3;
    const bool arow_ok = (m0 + arow) < M;
    const size_t abase = (size_t)(m0 + arow) * FF + aseg * 8;

    float acc[2][8][4];
#pragma unroll
    for (int mt = 0; mt < 2; ++mt)
#pragma unroll
        for (int nt = 0; nt < 8; ++nt)
#pragma unroll
            for (int e = 0; e < 4; ++e) acc[mt][nt][e] = 0.f;

    float4 ra0, ra1;
    auto lda_fetch = [&](int c) {
        if (arow_ok) {
            const size_t off = abase + (size_t)c * BK2;
            const float4* g0 = reinterpret_cast<const float4*>(&g_part[off]);
            const float4* g1 = reinterpret_cast<const float4*>(&g_part[(size_t)NN * FF + off]);
            const float4* g2 = reinterpret_cast<const float4*>(&g_part[(size_t)2 * NN * FF + off]);
            const float4* gx = reinterpret_cast<const float4*>(&inp[off]);
            float4 p0 = __ldg(g0), p1 = __ldg(g1), p2 = __ldg(g2), x = __ldg(gx);
            ra0.x = (p0.x + p1.x + p2.x) * INV_SCALE1 + alpha * x.x;
            ra0.y = (p0.y + p1.y + p2.y) * INV_SCALE1 + alpha * x.y;
            ra0.z = (p0.z + p1.z + p2.z) * INV_SCALE1 + alpha * x.z;
            ra0.w = (p0.w + p1.w + p2.w) * INV_SCALE1 + alpha * x.w;
            p0 = __ldg(g0 + 1); p1 = __ldg(g1 + 1); p2 = __ldg(g2 + 1); x = __ldg(gx + 1);
            ra1.x = (p0.x + p1.x + p2.x) * INV_SCALE1 + alpha * x.x;
            ra1.y = (p0.y + p1.y + p2.y) * INV_SCALE1 + alpha * x.y;
            ra1.z = (p0.z + p1.z + p2.z) * INV_SCALE1 + alpha * x.z;
            ra1.w = (p0.w + p1.w + p2.w) * INV_SCALE1 + alpha * x.w;
        } else {
            ra0 = make_float4(0.f, 0.f, 0.f, 0.f);
            ra1 = make_float4(0.f, 0.f, 0.f, 0.f);
        }
    };
    auto sts_a = [&](int c) {
        uint4 u;
        u.x = pack_h2(ra0.x, ra0.y);
        u.y = pack_h2(ra0.z, ra0.w);
        u.z = pack_h2(ra1.x, ra1.y);
        u.w = pack_h2(ra1.z, ra1.w);
        char* dst = sm2 + (c & (STAGES2 - 1)) * STAGE_BYTES2
                  + (size_t)arow * (PADA2 * 2) + aseg * 16;
        *reinterpret_cast<uint4*>(dst) = u;
    };
    auto issue_b = [&](int c) {
        const int s = c & (STAGES2 - 1);
        const uint32_t dbase = smem_u32(sm2 + s * STAGE_BYTES2) + A_BYTES2;
        const __half* gB = B16 + (size_t)c * BK2;
#pragma unroll
        for (int t = 0; t < 2; ++t) {
            const int idx = tid + t * 512;
            const int row = idx >> 2, seg = idx & 3;
            const uint32_t soff = (uint32_t)(row * PADB2 + seg * 8) * 2;
            cp_async16(dbase + soff, gB + (size_t)row * ldb + seg * 8);
        }
        cp_commit();
    };

    lda_fetch(0);
    for (int c = 0; c < STAGES2 - 1; ++c) issue_b(c);

    for (int c = 0; c < kChunks; ++c) {
        sts_a(c);
        cp_wait<STAGES2 - 2>();
        __syncthreads();
        if (c + 1 < kChunks) lda_fetch(c + 1);
        if (c + STAGES2 - 1 < kChunks) issue_b(c + STAGES2 - 1);
        else cp_commit();

        const char* stage = sm2 + (c & (STAGES2 - 1)) * STAGE_BYTES2;
        const uint32_t bA = smem_u32(stage) + aoff_lane;
        const uint32_t bB = smem_u32(stage + A_BYTES2) + boff_lane;

#pragma unroll
        for (int ks = 0; ks < BK2; ks += 16) {
            uint32_t af[2][4];
#pragma unroll
            for (int mt = 0; mt < 2; ++mt)
                ldmatrix_x4(af[mt][0], af[mt][1], af[mt][2], af[mt][3],
                            bA + (uint32_t)(mt * 16 * PADA2 * 2 + ks * 2));
            uint32_t bf[8][2];
#pragma unroll
            for (int i = 0; i < 4; ++i) {
                const uint32_t addr = bB + (uint32_t)(i * 16 * PADB2 * 2 + ks * 2);
                ldmatrix_x4(bf[2 * i][0], bf[2 * i][1],
                            bf[2 * i + 1][0], bf[2 * i + 1][1], addr);
            }
#pragma unroll
            for (int mt = 0; mt < 2; ++mt)
#pragma unroll
                for (int nt = 0; nt < 8; ++nt)
                    mma_fp16(acc[mt][nt], af[mt], bf[nt]);
        }
    }

    // epilogue: supportT16[cb*NN + r] = fp16(acc)
#pragma unroll
    for (int mt = 0; mt < 2; ++mt) {
#pragma unroll
        for (int half = 0; half < 2; ++half) {
            const int r = m0 + wm + mt * 16 + l4 + half * 8;
            if (r >= M) continue;
#pragma unroll
            for (int nt = 0; nt < 8; ++nt) {
                const int cb = wn + nt * 8 + lm * 2;
                g_supportT16[(size_t)cb * NN + r] =
                    __float2half_rn(acc[mt][nt][half * 2]);
                g_supportT16[(size_t)(cb + 1) * NN + r] =
                    __float2half_rn(acc[mt][nt][half * 2 + 1]);
            }
        }
    }
}

// ========================================================================
// reduction / prologue kernels
// ========================================================================
__global__ void reduce_sum_kernel(float* __restrict__ out) {
    const size_t i = ((size_t)blockIdx.x * blockDim.x + threadIdx.x) * 4;
    float4 p0 = *reinterpret_cast<const float4*>(&g_part[i]);
    float4 p1 = *reinterpret_cast<const float4*>(&g_part[(size_t)NN * FF + i]);
    float4 p2 = *reinterpret_cast<const float4*>(&g_part[(size_t)2 * NN * FF + i]);
    float4 r;
    r.x = p0.x + p1.x + p2.x;
    r.y = p0.y + p1.y + p2.y;
    r.z = p0.z + p1.z + p2.z;
    r.w = p0.w + p1.w + p2.w;
    *reinterpret_cast<float4*>(&out[i]) = r;
}

__global__ void scores_kernel(const float* __restrict__ input,
                              const float* __restrict__ attn) {
    const int gw   = (blockIdx.x * blockDim.x + threadIdx.x) >> 5;
    const int lane = threadIdx.x & 31;
    if (gw >= NN) return;
    const float* row = input + (size_t)gw * FF;
    float s = 0.f;
#pragma unroll
    for (int j = 0; j < FF / 32; ++j)
        s += row[lane + 32 * j] * __ldg(&attn[lane + 32 * j]);
#pragma unroll
    for (int o = 16; o; o >>= 1) s += __shfl_xor_sync(0xFFFFFFFFu, s, o);
    if (lane == 0) g_scores[gw] = s;
}

__global__ void softmax_kernel() {
    const int tid = threadIdx.x, lane = tid & 31, warp = tid >> 5;
    __shared__ float red[32];
    __shared__ float s_max, s_sum;
    float m = -3.4e38f;
    for (int i = tid; i < NN; i += 1024) m = fmaxf(m, g_scores[i]);
#pragma unroll
    for (int o = 16; o; o >>= 1) m = fmaxf(m, __shfl_xor_sync(0xFFFFFFFFu, m, o));
    if (lane == 0) red[warp] = m;
    __syncthreads();
    if (warp == 0) {
        m = red[lane];
#pragma unroll
        for (int o = 16; o; o >>= 1) m = fmaxf(m, __shfl_xor_sync(0xFFFFFFFFu, m, o));
        if (lane == 0) s_max = m;
    }
    __syncthreads();
    const float mx = s_max;
    float s = 0.f;
    for (int i = tid; i < NN; i += 1024) s += expf(g_scores[i] - mx);
#pragma unroll
    for (int o = 16; o; o >>= 1) s += __shfl_xor_sync(0xFFFFFFFFu, s, o);
    if (lane == 0) red[warp] = s;
    __syncthreads();
    if (warp == 0) {
        s = red[lane];
#pragma unroll
        for (int o = 16; o; o >>= 1) s += __shfl_xor_sync(0xFFFFFFFFu, s, o);
        if (lane == 0) s_sum = s;
    }
    __syncthreads();
    const float inv = 1.0f / s_sum;
    for (int i = tid; i < NN; i += 1024) g_p[i] = expf(g_scores[i] - mx) * inv;
}

// scaledT16[f, i] = fp16( p[i] * input[i, f] * 2^14 )
__global__ void scaledT_kernel(const float* __restrict__ input) {
    __shared__ float t[32][33];
    const int tx = threadIdx.x, ty = threadIdx.y;
    const int i0 = blockIdx.x * 32, f0 = blockIdx.y * 32;
    const int i = i0 + ty, f = f0 + tx;
    t[ty][tx] = g_p[i] * SCALE1 * input[(size_t)i * FF + f];
    __syncthreads();
    g_scaledT16[(size_t)(f0 + ty) * NN + i0 + tx] = __float2half_rn(t[tx][ty]);
}

// weightT16[o, i] = fp16( weight[i, o] )
__global__ void weightT_kernel(const float* __restrict__ weight) {
    __shared__ float t[32][33];
    const int tx = threadIdx.x, ty = threadIdx.y;
    const int i0 = blockIdx.x * 32, o0 = blockIdx.y * 32;
    t[ty][tx] = weight[(size_t)(i0 + ty) * FF + o0 + tx];
    __syncthreads();
    g_weightT16[(size_t)(o0 + ty) * FF + i0 + tx] = __float2half_rn(t[tx][ty]);
}

// ========================================================================
// launch
// ========================================================================
extern "C" void kernel_launch(void* const* d_in, const int* in_sizes, int n_in,
                              void* d_out, int out_size) {
    const float* input  = (const float*)d_in[0];
    const float* adj    = (const float*)d_in[1];
    const float* inc    = (const float*)d_in[2];
    const float* weight = (const float*)d_in[3];
    const float* attn   = (const float*)d_in[4];
    const float* alpha  = (const float*)d_in[5];
    float* out = (float*)d_out;

    cudaFuncSetAttribute(gemm_h16,
                         cudaFuncAttributeMaxDynamicSharedMemorySize, DYN_SMEM2);
    cudaFuncSetAttribute(gemm2_fused,
                         cudaFuncAttributeMaxDynamicSharedMemorySize, DYN_SMEM2);

    __half *scaledT16, *supportT16, *weightT16;
    float* part;
    cudaGetSymbolAddress((void**)&scaledT16,  g_scaledT16);
    cudaGetSymbolAddress((void**)&supportT16, g_supportT16);
    cudaGetSymbolAddress((void**)&weightT16,  g_weightT16);
    cudaGetSymbolAddress((void**)&part,       g_part);

    scores_kernel<<<(NN + 7) / 8, 256>>>(input, attn);
    softmax_kernel<<<1, 1024>>>();
    scaledT_kernel<<<dim3(NN / 32, FF / 32), dim3(32, 32)>>>(input);
    weightT_kernel<<<dim3(FF / 32, FF / 32), dim3(32, 32)>>>(weight);

    const int gridM = (NN + BM - 1) / BM;        // 94
    const int redBlocks = (NN * FF / 4) / 1024;  // 750

    // GEMM1 (fp16, B pre-scaled by 2^14): partials of adj @ scaled
    gemm_h16<<<dim3(gridM, SPLITK), 512, DYN_SMEM2>>>(
        adj, NN, scaledT16, NN, NN, KCH_BIG2, part);

    // GEMM2 fused: A = sum(part)*2^-14 + alpha*input; writes supportT16^T
    gemm2_fused<<<dim3(gridM, 1), 512, DYN_SMEM2>>>(input, alpha, weightT16, NN);

    // GEMM3 (fp16): partials of incidence @ support
    gemm_h16<<<dim3(gridM, SPLITK), 512, DYN_SMEM2>>>(
        inc, NN, supportT16, NN, NN, KCH_BIG2, part);
    reduce_sum_kernel<<<redBlocks, 1024>>>(out);

    (void)in_sizes; (void)n_in; (void)out_size;
}